// round 12
// baseline (speedup 1.0000x reference)
#include <cuda_runtime.h>
#include <cuda_bf16.h>
#include <math.h>

// ---------------- problem constants ----------------
#define EMB 128
#define HID 256
#define EDIM 16
#define NGRAPH 512
#define NLAYER 3
#define MAXN 100352
#define MAXE 600064

// ---------------- scratch (device globals) ----------------
__device__ float g_hinA[(size_t)MAXN * EMB];
__device__ float g_hinB[(size_t)MAXN * EMB];
__device__ __nv_bfloat16 g_x[(size_t)MAXN * EMB];
__device__ float g_vn [NGRAPH * EMB];
__device__ float g_vt [NGRAPH * EMB];
// CSR scratch
__device__ int g_deg [MAXN];
__device__ int g_off [MAXN + 1];
__device__ int g_cur [MAXN];
__device__ int g_part[256];
__device__ int g_eids[MAXE];
__device__ int g_ssrc[MAXE];

// ---------------- helpers ----------------
__device__ __forceinline__ void red_add_v4(float* p, float4 v) {
    asm volatile("red.global.add.v4.f32 [%0], {%1,%2,%3,%4};"
                 :: "l"(p), "f"(v.x), "f"(v.y), "f"(v.z), "f"(v.w) : "memory");
}
__device__ __forceinline__ void mma_tf32(float* c, const unsigned* a, unsigned b0, unsigned b1) {
    asm volatile("mma.sync.aligned.m16n8k8.row.col.f32.tf32.tf32.f32 "
                 "{%0,%1,%2,%3},{%4,%5,%6,%7},{%8,%9},{%0,%1,%2,%3};"
                 : "+f"(c[0]), "+f"(c[1]), "+f"(c[2]), "+f"(c[3])
                 : "r"(a[0]), "r"(a[1]), "r"(a[2]), "r"(a[3]), "r"(b0), "r"(b1));
}
__device__ __forceinline__ void cp_async16(float* smem, const float* gmem) {
    unsigned s = (unsigned)__cvta_generic_to_shared(smem);
    asm volatile("cp.async.cg.shared.global [%0], [%1], 16;" :: "r"(s), "l"(gmem));
}
#define CP_COMMIT() asm volatile("cp.async.commit_group;")
#define CP_WAIT1()  asm volatile("cp.async.wait_group 1;")
#define CP_WAIT0()  asm volatile("cp.async.wait_group 0;")

// ================= CSR build (once per launch) =================
__global__ void k_count(const int* __restrict__ eidx, int* __restrict__ deg, int E) {
    int e = blockIdx.x * blockDim.x + threadIdx.x;
    if (e < E) atomicAdd(&deg[eidx[E + e]], 1);
}

__global__ void k_scan1(const int* __restrict__ deg, int* __restrict__ off,
                        int* __restrict__ part, int N) {
    __shared__ int wsum[16];
    int i = blockIdx.x * 512 + threadIdx.x;
    int lane = threadIdx.x & 31, w = threadIdx.x >> 5;
    int v = (i < N) ? deg[i] : 0;
    int x = v;
#pragma unroll
    for (int d = 1; d < 32; d <<= 1) { int y = __shfl_up_sync(0xffffffffu, x, d); if (lane >= d) x += y; }
    if (lane == 31) wsum[w] = x;
    __syncthreads();
    if (w == 0) {
        int s = (lane < 16) ? wsum[lane] : 0;
#pragma unroll
        for (int d = 1; d < 16; d <<= 1) { int y = __shfl_up_sync(0xffffffffu, s, d); if (lane >= d) s += y; }
        if (lane < 16) wsum[lane] = s;
    }
    __syncthreads();
    int base = (w > 0) ? wsum[w - 1] : 0;
    if (i < N) off[i] = base + x - v;
    if (threadIdx.x == 0) part[blockIdx.x] = wsum[15];
}

__global__ void k_scan2(int* __restrict__ part) {
    __shared__ int wsum[8];
    int tid = threadIdx.x;
    int lane = tid & 31, w = tid >> 5;
    int v = part[tid];
    int x = v;
#pragma unroll
    for (int d = 1; d < 32; d <<= 1) { int y = __shfl_up_sync(0xffffffffu, x, d); if (lane >= d) x += y; }
    if (lane == 31) wsum[w] = x;
    __syncthreads();
    if (w == 0) {
        int s = (lane < 8) ? wsum[lane] : 0;
#pragma unroll
        for (int d = 1; d < 8; d <<= 1) { int y = __shfl_up_sync(0xffffffffu, s, d); if (lane >= d) s += y; }
        if (lane < 8) wsum[lane] = s;
    }
    __syncthreads();
    int base = (w > 0) ? wsum[w - 1] : 0;
    part[tid] = base + x - v;
}

__global__ void k_scan3(int* __restrict__ off, int* __restrict__ cur,
                        const int* __restrict__ part, int N, int E) {
    int i = blockIdx.x * 512 + threadIdx.x;
    if (i < N) {
        int o = off[i] + part[blockIdx.x];
        off[i] = o;
        cur[i] = o;
    }
    if (i == 0) off[N] = E;
}

__global__ void k_scatter(const int* __restrict__ eidx, int* __restrict__ cur,
                          int* __restrict__ eids, int* __restrict__ ssrc, int E) {
    int e = blockIdx.x * blockDim.x + threadIdx.x;
    if (e < E) {
        int pos = atomicAdd(&cur[eidx[E + e]], 1);
        eids[pos] = e;
        ssrc[pos] = eidx[e];
    }
}

// ---------------- kernel 0: init vn ----------------
__global__ void k_init_vn(const float* __restrict__ vn_emb, float* __restrict__ vn) {
    int i = blockIdx.x * blockDim.x + threadIdx.x;
    if (i < NGRAPH * EMB) vn[i] = vn_emb[i & (EMB - 1)];
}

// ---------------- kernel 1: hin = h + vn[batch]; vt += segsum(hin) (layer 0) ----------------
__global__ void k_hin_vt(const float* __restrict__ h, const int* __restrict__ batch,
                         const float* __restrict__ vn, float* __restrict__ hin,
                         float* __restrict__ vt, int N) {
    int lane = threadIdx.x;
    int row  = threadIdx.y;
    int base = blockIdx.x * 64;
    float4 acc = make_float4(0.f, 0.f, 0.f, 0.f);
    int gcur = -1;
    for (int it = 0; it < 8; it++) {
        int i = base + it * 8 + row;
        if (i >= N) break;
        int g = batch[i];
        const float4 hv = *(const float4*)&h[(size_t)i * EMB + lane * 4];
        const float4 vv = *(const float4*)&vn[(size_t)g * EMB + lane * 4];
        float4 s = make_float4(hv.x + vv.x, hv.y + vv.y, hv.z + vv.z, hv.w + vv.w);
        *(float4*)&hin[(size_t)i * EMB + lane * 4] = s;
        if (g != gcur) {
            if (gcur >= 0) red_add_v4(&vt[(size_t)gcur * EMB + lane * 4], acc);
            acc = make_float4(0.f, 0.f, 0.f, 0.f);
            gcur = g;
        }
        acc.x += s.x; acc.y += s.y; acc.z += s.z; acc.w += s.w;
    }
    if (gcur >= 0) red_add_v4(&vt[(size_t)gcur * EMB + lane * 4], acc);
}

// ---------------- kernel 1b: vt += segsum(hin) ----------------
__global__ void k_vt(const float* __restrict__ hin, const int* __restrict__ batch,
                     float* __restrict__ vt, int N) {
    int lane = threadIdx.x;
    int row  = threadIdx.y;
    int base = blockIdx.x * 64;
    float4 acc = make_float4(0.f, 0.f, 0.f, 0.f);
    int gcur = -1;
    for (int it = 0; it < 8; it++) {
        int i = base + it * 8 + row;
        if (i >= N) break;
        int g = batch[i];
        const float4 s = *(const float4*)&hin[(size_t)i * EMB + lane * 4];
        if (g != gcur) {
            if (gcur >= 0) red_add_v4(&vt[(size_t)gcur * EMB + lane * 4], acc);
            acc = make_float4(0.f, 0.f, 0.f, 0.f);
            gcur = g;
        }
        acc.x += s.x; acc.y += s.y; acc.z += s.z; acc.w += s.w;
    }
    if (gcur >= 0) red_add_v4(&vt[(size_t)gcur * EMB + lane * 4], acc);
}

// ---------------- kernel 2: FUSED edge-emb GEMM (smem) + CSR aggregation ----------------
// CTA = 32 consecutive nodes -> contiguous CSR position range [off[n0], off[n0+32]).
// Loop over 64-edge chunks: stage ea -> tf32 GEMM -> emb tile in SMEM (fp32) -> consume.
// x(bf16) = hin[node] + sum relu(hin[ssrc[p]] + emb[p]); emb never touches DRAM.
#define AS_STR 20
#define WE_STR 136
#define ET_STR 132

__global__ __launch_bounds__(256, 2) void k_fused_agg(
    const float* __restrict__ hin, const float* __restrict__ ea,
    const int* __restrict__ ssrc, const int* __restrict__ off,
    const int* __restrict__ eids, const float* __restrict__ We,
    const float* __restrict__ be, __nv_bfloat16* __restrict__ xout,
    int N, int E) {
    __shared__ float As[64 * AS_STR];      // 5.1 KB
    __shared__ float sW[EDIM * WE_STR];    // 8.7 KB
    __shared__ float embt[64 * ET_STR];    // 33.8 KB

    int tid = threadIdx.x;
    int wid = tid >> 5, lane = tid & 31;
    int g = lane >> 2, t = lane & 3;
    int warp_m = wid >> 2;   // 0..1
    int warp_n = wid & 3;    // 0..3
    int n0 = blockIdx.x * 32;

    // stage We once
#pragma unroll
    for (int p = 0; p < 8; p++) {
        int li = tid + p * 256;
        int k = li >> 7, c = li & 127;
        sW[k * WE_STR + c] = We[k * EMB + c];
    }

    // node state: warp owns 4 nodes
    int nbeg[4], nend[4];
    float4 acc[4];
#pragma unroll
    for (int i = 0; i < 4; i++) {
        int node = n0 + wid * 4 + i;
        if (node < N) { nbeg[i] = off[node]; nend[i] = off[node + 1]; }
        else          { nbeg[i] = 0;         nend[i] = 0; }
        acc[i] = make_float4(0.f, 0.f, 0.f, 0.f);
    }

    int P0 = off[n0];
    int n1 = n0 + 32; if (n1 > N) n1 = N;
    int P1 = (n0 < N) ? off[n1] : P0;

    for (int cbase = P0; cbase < P1; cbase += 64) {
        int cend = cbase + 64; if (cend > P1) cend = P1;

        // ---- stage ea rows for this chunk (64 x 16) ----
        __syncthreads();   // protect As/embt from previous chunk consumers
        {
            int row = tid >> 2, cg = tid & 3;
            int pos = cbase + row;
            float4 v = make_float4(0.f, 0.f, 0.f, 0.f);
            if (pos < cend) {
                int eid = eids[pos];
                v = *(const float4*)&ea[(size_t)eid * EDIM + cg * 4];
            }
            float* d = &As[row * AS_STR + cg * 4];
            d[0] = v.x; d[1] = v.y; d[2] = v.z; d[3] = v.w;
        }
        __syncthreads();

        // ---- GEMM [64x16]@[16x128] -> embt (fp32, +bias) ----
        float c[2][4][4];
#pragma unroll
        for (int mt = 0; mt < 2; mt++)
#pragma unroll
            for (int nt = 0; nt < 4; nt++)
#pragma unroll
                for (int j = 0; j < 4; j++) c[mt][nt][j] = 0.f;

#pragma unroll
        for (int ks = 0; ks < 2; ks++) {
            int kl = ks * 8;
            unsigned a[2][4];
#pragma unroll
            for (int mt = 0; mt < 2; mt++) {
                int r = warp_m * 32 + mt * 16 + g;
                a[mt][0] = __float_as_uint(As[r * AS_STR + kl + t]);
                a[mt][1] = __float_as_uint(As[(r + 8) * AS_STR + kl + t]);
                a[mt][2] = __float_as_uint(As[r * AS_STR + kl + t + 4]);
                a[mt][3] = __float_as_uint(As[(r + 8) * AS_STR + kl + t + 4]);
            }
#pragma unroll
            for (int nt = 0; nt < 4; nt++) {
                int col = warp_n * 32 + nt * 8 + g;
                unsigned b0 = __float_as_uint(sW[(kl + t) * WE_STR + col]);
                unsigned b1r = __float_as_uint(sW[(kl + t + 4) * WE_STR + col]);
                mma_tf32(c[0][nt], a[0], b0, b1r);
                mma_tf32(c[1][nt], a[1], b0, b1r);
            }
        }

#pragma unroll
        for (int nt = 0; nt < 4; nt++) {
            int col = warp_n * 32 + nt * 8 + t * 2;
            float bv0 = __ldg(&be[col]), bv1 = __ldg(&be[col + 1]);
#pragma unroll
            for (int mt = 0; mt < 2; mt++) {
#pragma unroll
                for (int half = 0; half < 2; half++) {
                    int row = warp_m * 32 + mt * 16 + g + half * 8;
                    embt[row * ET_STR + col]     = c[mt][nt][half * 2]     + bv0;
                    embt[row * ET_STR + col + 1] = c[mt][nt][half * 2 + 1] + bv1;
                }
            }
        }
        __syncthreads();

        // ---- consume: each warp walks its nodes' positions within this chunk ----
#pragma unroll
        for (int i = 0; i < 4; i++) {
            int s = nbeg[i] > cbase ? nbeg[i] : cbase;
            int e = nend[i] < cend  ? nend[i] : cend;
            int p = s;
            for (; p + 2 <= e; p += 2) {
                int s0 = ssrc[p], s1 = ssrc[p + 1];
                float4 e0 = *(const float4*)&embt[(p - cbase) * ET_STR + lane * 4];
                float4 e1 = *(const float4*)&embt[(p + 1 - cbase) * ET_STR + lane * 4];
                float4 x0 = *(const float4*)&hin[(size_t)s0 * EMB + lane * 4];
                float4 x1 = *(const float4*)&hin[(size_t)s1 * EMB + lane * 4];
                acc[i].x += fmaxf(x0.x + e0.x, 0.f) + fmaxf(x1.x + e1.x, 0.f);
                acc[i].y += fmaxf(x0.y + e0.y, 0.f) + fmaxf(x1.y + e1.y, 0.f);
                acc[i].z += fmaxf(x0.z + e0.z, 0.f) + fmaxf(x1.z + e1.z, 0.f);
                acc[i].w += fmaxf(x0.w + e0.w, 0.f) + fmaxf(x1.w + e1.w, 0.f);
            }
            if (p < e) {
                int s0 = ssrc[p];
                float4 e0 = *(const float4*)&embt[(p - cbase) * ET_STR + lane * 4];
                float4 x0 = *(const float4*)&hin[(size_t)s0 * EMB + lane * 4];
                acc[i].x += fmaxf(x0.x + e0.x, 0.f);
                acc[i].y += fmaxf(x0.y + e0.y, 0.f);
                acc[i].z += fmaxf(x0.z + e0.z, 0.f);
                acc[i].w += fmaxf(x0.w + e0.w, 0.f);
            }
        }
    }

    // ---- finalize: x = hin[node] + acc, store bf16 ----
#pragma unroll
    for (int i = 0; i < 4; i++) {
        int node = n0 + wid * 4 + i;
        if (node < N) {
            float4 hn = *(const float4*)&hin[(size_t)node * EMB + lane * 4];
            float4 v = make_float4(acc[i].x + hn.x, acc[i].y + hn.y,
                                   acc[i].z + hn.z, acc[i].w + hn.w);
            __nv_bfloat162 p0 = __floats2bfloat162_rn(v.x, v.y);
            __nv_bfloat162 p1 = __floats2bfloat162_rn(v.z, v.w);
            uint2 o;
            o.x = *(unsigned*)&p0;
            o.y = *(unsigned*)&p1;
            *(uint2*)&xout[(size_t)node * EMB + lane * 4] = o;
        }
    }
}

// ---------------- kernel 3: tensor-core node MLP (tf32, cp.async, occ=2, fused hin_next) ----------------
#define XS_STR 132
#define HS_STR 260
#define W1_STR 264
#define W2_STR 136
#define UB_FLOATS (64 * HS_STR)
#define WD_FLOATS (2 * 32 * W2_STR)
#define MLP_SMEM_FLOATS (UB_FLOATS + WD_FLOATS)

__global__ __launch_bounds__(256, 2) void k_node_mlp(
    const __nv_bfloat16* __restrict__ xin, const float* __restrict__ hin,
    const float* __restrict__ W1, const float* __restrict__ b1,
    const float* __restrict__ W2, const float* __restrict__ b2,
    const float* __restrict__ gamma, const float* __restrict__ beta,
    float* __restrict__ out, const float* __restrict__ vnn,
    const int* __restrict__ batch, int N, int mode, float inv) {
    extern __shared__ float smf[];
    float* Xs = smf;
    float* Hs = smf;
    float* Wd = smf + UB_FLOATS;

    int tid = threadIdx.x;
    int wid = tid >> 5, lane = tid & 31;
    int g = lane >> 2, t = lane & 3;
    int warp_m = wid >> 2;
    int warp_n = wid & 3;
    int base = blockIdx.x * 64;

#pragma unroll
    for (int p = 0; p < 8; p++) {
        int li = tid + p * 256;
        int row = li >> 5;
        int c4 = (li & 31) * 4;
        int node = base + row;
        float4 v = make_float4(0.f, 0.f, 0.f, 0.f);
        if (node < N) {
            uint2 u = *(const uint2*)&xin[(size_t)node * EMB + c4];
            v.x = __uint_as_float(u.x << 16);
            v.y = __uint_as_float(u.x & 0xFFFF0000u);
            v.z = __uint_as_float(u.y << 16);
            v.w = __uint_as_float(u.y & 0xFFFF0000u);
        }
        *(float4*)&Xs[row * XS_STR + c4] = v;
    }

    float c1[2][8][4];
#pragma unroll
    for (int mt = 0; mt < 2; mt++)
#pragma unroll
        for (int nt = 0; nt < 8; nt++)
#pragma unroll
            for (int j = 0; j < 4; j++) c1[mt][nt][j] = 0.f;

    {
#pragma unroll
        for (int p = 0; p < 4; p++) {
            int idx4 = tid + p * 256;
            int row = idx4 >> 6, c4 = idx4 & 63;
            cp_async16(&Wd[row * W1_STR + c4 * 4], &W1[(size_t)row * 256 + c4 * 4]);
        }
        CP_COMMIT();
    }

    for (int kc = 0; kc < 8; kc++) {
        if (kc < 7) {
            float* db = Wd + ((kc + 1) & 1) * (16 * W1_STR);
#pragma unroll
            for (int p = 0; p < 4; p++) {
                int idx4 = tid + p * 256;
                int row = idx4 >> 6, c4 = idx4 & 63;
                cp_async16(&db[row * W1_STR + c4 * 4],
                           &W1[(size_t)((kc + 1) * 16 + row) * 256 + c4 * 4]);
            }
            CP_COMMIT();
            CP_WAIT1();
        } else {
            CP_WAIT0();
        }
        __syncthreads();
        const float* Wb = Wd + (kc & 1) * (16 * W1_STR);
#pragma unroll
        for (int ks = 0; ks < 2; ks++) {
            int kl = ks * 8;
            int kg = kc * 16 + kl;
            unsigned a[2][4];
#pragma unroll
            for (int mt = 0; mt < 2; mt++) {
                int r = warp_m * 32 + mt * 16 + g;
                const float* x0 = &Xs[r * XS_STR + kg + t];
                const float* x8 = &Xs[(r + 8) * XS_STR + kg + t];
                a[mt][0] = __float_as_uint(x0[0]);
                a[mt][1] = __float_as_uint(x8[0]);
                a[mt][2] = __float_as_uint(x0[4]);
                a[mt][3] = __float_as_uint(x8[4]);
            }
#pragma unroll
            for (int nt = 0; nt < 8; nt++) {
                int col = warp_n * 64 + nt * 8 + g;
                unsigned b0 = __float_as_uint(Wb[(kl + t) * W1_STR + col]);
                unsigned b1r = __float_as_uint(Wb[(kl + t + 4) * W1_STR + col]);
                mma_tf32(c1[0][nt], a[0], b0, b1r);
                mma_tf32(c1[1][nt], a[1], b0, b1r);
            }
        }
        __syncthreads();
    }

#pragma unroll
    for (int nt = 0; nt < 8; nt++) {
        int c0 = warp_n * 64 + nt * 8 + t * 2;
        float bb0 = __ldg(&b1[c0]);
        float bb1 = __ldg(&b1[c0 + 1]);
#pragma unroll
        for (int mt = 0; mt < 2; mt++) {
            int r = warp_m * 32 + mt * 16 + g;
            Hs[r * HS_STR + c0]           = fmaxf(c1[mt][nt][0] + bb0, 0.f);
            Hs[r * HS_STR + c0 + 1]       = fmaxf(c1[mt][nt][1] + bb1, 0.f);
            Hs[(r + 8) * HS_STR + c0]     = fmaxf(c1[mt][nt][2] + bb0, 0.f);
            Hs[(r + 8) * HS_STR + c0 + 1] = fmaxf(c1[mt][nt][3] + bb1, 0.f);
        }
    }

    float c2[2][4][4];
#pragma unroll
    for (int mt = 0; mt < 2; mt++)
#pragma unroll
        for (int nt = 0; nt < 4; nt++)
#pragma unroll
            for (int j = 0; j < 4; j++) c2[mt][nt][j] = 0.f;

    {
#pragma unroll
        for (int p = 0; p < 4; p++) {
            int idx4 = tid + p * 256;
            int row = idx4 >> 5, c4 = idx4 & 31;
            cp_async16(&Wd[row * W2_STR + c4 * 4], &W2[(size_t)row * 128 + c4 * 4]);
        }
        CP_COMMIT();
    }

    for (int kc = 0; kc < 8; kc++) {
        if (kc < 7) {
            float* db = Wd + ((kc + 1) & 1) * (32 * W2_STR);
#pragma unroll
            for (int p = 0; p < 4; p++) {
                int idx4 = tid + p * 256;
                int row = idx4 >> 5, c4 = idx4 & 31;
                cp_async16(&db[row * W2_STR + c4 * 4],
                           &W2[(size_t)((kc + 1) * 32 + row) * 128 + c4 * 4]);
            }
            CP_COMMIT();
            CP_WAIT1();
        } else {
            CP_WAIT0();
        }
        __syncthreads();
        const float* Wb = Wd + (kc & 1) * (32 * W2_STR);
#pragma unroll
        for (int ks = 0; ks < 4; ks++) {
            int kl = ks * 8;
            int kg = kc * 32 + kl;
            unsigned a[2][4];
#pragma unroll
            for (int mt = 0; mt < 2; mt++) {
                int r = warp_m * 32 + mt * 16 + g;
                const float* x0 = &Hs[r * HS_STR + kg + t];
                const float* x8 = &Hs[(r + 8) * HS_STR + kg + t];
                a[mt][0] = __float_as_uint(x0[0]);
                a[mt][1] = __float_as_uint(x8[0]);
                a[mt][2] = __float_as_uint(x0[4]);
                a[mt][3] = __float_as_uint(x8[4]);
            }
#pragma unroll
            for (int nt = 0; nt < 4; nt++) {
                int col = warp_n * 32 + nt * 8 + g;
                unsigned b0 = __float_as_uint(Wb[(kl + t) * W2_STR + col]);
                unsigned b1r = __float_as_uint(Wb[(kl + t + 4) * W2_STR + col]);
                mma_tf32(c2[0][nt], a[0], b0, b1r);
                mma_tf32(c2[1][nt], a[1], b0, b1r);
            }
        }
        __syncthreads();
    }

    int bg[2][2];
    if (mode) {
#pragma unroll
        for (int mt = 0; mt < 2; mt++)
#pragma unroll
            for (int half = 0; half < 2; half++) {
                int node = base + warp_m * 32 + mt * 16 + g + half * 8;
                bg[mt][half] = (node < N) ? batch[node] : 0;
            }
    }
#pragma unroll
    for (int nt = 0; nt < 4; nt++) {
        int col = warp_n * 32 + nt * 8 + t * 2;
        float bv0 = __ldg(&b2[col]),          bv1 = __ldg(&b2[col + 1]);
        float gv0 = __ldg(&gamma[col]) * inv, gv1 = __ldg(&gamma[col + 1]) * inv;
        float ev0 = __ldg(&beta[col]),        ev1 = __ldg(&beta[col + 1]);
#pragma unroll
        for (int mt = 0; mt < 2; mt++) {
#pragma unroll
            for (int half = 0; half < 2; half++) {
                int row = warp_m * 32 + mt * 16 + g + half * 8;
                int node = base + row;
                if (node < N) {
                    float z0 = c2[mt][nt][half * 2]     + bv0;
                    float z1 = c2[mt][nt][half * 2 + 1] + bv1;
                    z0 = z0 * gv0 + ev0;
                    z1 = z1 * gv1 + ev1;
                    if (mode) { z0 = fmaxf(z0, 0.f); z1 = fmaxf(z1, 0.f); }
                    float2 hr = *(const float2*)&hin[(size_t)node * EMB + col];
                    z0 += hr.x; z1 += hr.y;
                    if (mode) {
                        float2 vv = *(const float2*)&vnn[(size_t)bg[mt][half] * EMB + col];
                        z0 += vv.x; z1 += vv.y;
                    }
                    *(float2*)&out[(size_t)node * EMB + col] = make_float2(z0, z1);
                }
            }
        }
    }
}

// ---------------- kernel 4: virtual-node MLP ----------------
__global__ __launch_bounds__(256) void k_vn_mlp(
    const float* __restrict__ vt, float* __restrict__ vn,
    const float* __restrict__ w1, const float* __restrict__ b1,
    const float* __restrict__ g1, const float* __restrict__ be1,
    const float* __restrict__ w2, const float* __restrict__ b2,
    const float* __restrict__ g2, const float* __restrict__ be2, float inv) {
    __shared__ float sv[EMB];
    __shared__ float sm1[HID];
    int g = blockIdx.x;
    int tid = threadIdx.x;
    if (tid < EMB) sv[tid] = vt[(size_t)g * EMB + tid] + vn[(size_t)g * EMB + tid];
    __syncthreads();
    {
        int j = tid;
        float s = b1[j];
#pragma unroll 8
        for (int k = 0; k < EMB; k++) s += sv[k] * w1[(size_t)k * HID + j];
        s = s * (g1[j] * inv) + be1[j];
        sm1[j] = fmaxf(s, 0.f);
    }
    __syncthreads();
    if (tid < EMB) {
        int c = tid;
        float s = b2[c];
#pragma unroll 8
        for (int j = 0; j < HID; j++) s += sm1[j] * w2[(size_t)j * EMB + c];
        s = s * (g2[c] * inv) + be2[c];
        vn[(size_t)g * EMB + c] += fmaxf(s, 0.f);
    }
}

// ---------------- host orchestration ----------------
extern "C" void kernel_launch(void* const* d_in, const int* in_sizes, int n_in,
                              void* d_out, int out_size) {
    if (n_in < 21) return;

    const float* input_feature = (const float*)d_in[0];
    const int* edge_index;
    const float* edge_attr;
    long long E;
    if ((long long)in_sizes[1] < (long long)in_sizes[2]) {
        edge_index = (const int*)d_in[1];
        edge_attr  = (const float*)d_in[2];
        E = in_sizes[1] / 2;
    } else {
        edge_index = (const int*)d_in[2];
        edge_attr  = (const float*)d_in[1];
        E = in_sizes[2] / 2;
    }
    const int* batch = (const int*)d_in[3];
    int N = in_sizes[0] / EMB;

    const float* vn_emb = (const float*)d_in[4];
    const float* cew = (const float*)d_in[5];
    const float* ceb = (const float*)d_in[6];
    const float* cw1 = (const float*)d_in[7];
    const float* cb1 = (const float*)d_in[8];
    const float* cw2 = (const float*)d_in[9];
    const float* cb2 = (const float*)d_in[10];
    const float* bng = (const float*)d_in[11];
    const float* bnb = (const float*)d_in[12];
    const float* vw1 = (const float*)d_in[13];
    const float* vb1 = (const float*)d_in[14];
    const float* vg1 = (const float*)d_in[15];
    const float* vbe1 = (const float*)d_in[16];
    const float* vw2 = (const float*)d_in[17];
    const float* vb2 = (const float*)d_in[18];
    const float* vg2 = (const float*)d_in[19];
    const float* vbe2 = (const float*)d_in[20];

    float *hinA, *hinB, *vn, *vt;
    __nv_bfloat16 *xbuf;
    int *deg, *off, *cur, *part, *eids, *ssrc;
    cudaGetSymbolAddress((void**)&hinA, g_hinA);
    cudaGetSymbolAddress((void**)&hinB, g_hinB);
    cudaGetSymbolAddress((void**)&xbuf, g_x);
    cudaGetSymbolAddress((void**)&vn, g_vn);
    cudaGetSymbolAddress((void**)&vt, g_vt);
    cudaGetSymbolAddress((void**)&deg, g_deg);
    cudaGetSymbolAddress((void**)&off, g_off);
    cudaGetSymbolAddress((void**)&cur, g_cur);
    cudaGetSymbolAddress((void**)&part, g_part);
    cudaGetSymbolAddress((void**)&eids, g_eids);
    cudaGetSymbolAddress((void**)&ssrc, g_ssrc);

    cudaFuncSetAttribute(k_node_mlp, cudaFuncAttributeMaxDynamicSharedMemorySize,
                         MLP_SMEM_FLOATS * (int)sizeof(float));

    const float inv = 1.0f / sqrtf(1.0f + 1e-5f);

    // ---- CSR build ----
    int NB = (N + 511) / 512;
    cudaMemsetAsync(deg, 0, (size_t)N * sizeof(int));
    cudaMemsetAsync(part, 0, 256 * sizeof(int));
    k_count<<<(int)((E + 255) / 256), 256>>>(edge_index, deg, (int)E);
    k_scan1<<<NB, 512>>>(deg, off, part, N);
    k_scan2<<<1, 256>>>(part);
    k_scan3<<<NB, 512>>>(off, cur, part, N, (int)E);
    k_scatter<<<(int)((E + 255) / 256), 256>>>(edge_index, cur, eids, ssrc, (int)E);

    k_init_vn<<<(NGRAPH * EMB + 255) / 256, 256>>>(vn_emb, vn);

    int nblk = (N + 63) / 64;
    int fblk = (N + 31) / 32;
    size_t mlp_smem = MLP_SMEM_FLOATS * sizeof(float);

    cudaMemsetAsync(vt, 0, (size_t)NGRAPH * EMB * sizeof(float));
    k_hin_vt<<<nblk, dim3(32, 8)>>>(input_feature, batch, vn, hinA, vt, N);

    float* hin_cur = hinA;
    float* hin_nxt = hinB;
    for (int l = 0; l < NLAYER; l++) {
        int last = (l == NLAYER - 1);

        k_fused_agg<<<fblk, 256>>>(hin_cur, edge_attr, ssrc, off, eids,
                                   cew + (size_t)l * EDIM * EMB, ceb + (size_t)l * EMB,
                                   xbuf, N, (int)E);

        if (!last) {
            k_vn_mlp<<<NGRAPH, 256>>>(vt, vn,
                                      vw1 + (size_t)l * EMB * HID, vb1 + (size_t)l * HID,
                                      vg1 + (size_t)l * HID, vbe1 + (size_t)l * HID,
                                      vw2 + (size_t)l * HID * EMB, vb2 + (size_t)l * EMB,
                                      vg2 + (size_t)l * EMB, vbe2 + (size_t)l * EMB, inv);
        }

        float* outp = last ? (float*)d_out : hin_nxt;
        k_node_mlp<<<nblk, 256, mlp_smem>>>(
            xbuf, hin_cur,
            cw1 + (size_t)l * EMB * HID, cb1 + (size_t)l * HID,
            cw2 + (size_t)l * HID * EMB, cb2 + (size_t)l * EMB,
            bng + (size_t)l * EMB, bnb + (size_t)l * EMB,
            outp, vn, batch, N, last ? 0 : 1, inv);

        if (l == 0) {
            cudaMemsetAsync(vt, 0, (size_t)NGRAPH * EMB * sizeof(float));
            k_vt<<<nblk, dim3(32, 8)>>>(hin_nxt, batch, vt, N);
        }

        float* tmp = hin_cur; hin_cur = hin_nxt; hin_nxt = tmp;
    }
}

// round 13
// speedup vs baseline: 1.3126x; 1.3126x over previous
#include <cuda_runtime.h>
#include <cuda_bf16.h>
#include <math.h>

// ---------------- problem constants ----------------
#define EMB 128
#define HID 256
#define EDIM 16
#define NGRAPH 512
#define NLAYER 3
#define MAXN 100352
#define MAXE 600064

// ---------------- scratch (device globals) ----------------
__device__ float g_hinA[(size_t)MAXN * EMB];
__device__ float g_hinB[(size_t)MAXN * EMB];
__device__ __nv_bfloat16 g_x[(size_t)MAXN * EMB];
__device__ __nv_bfloat16 g_emb[(size_t)MAXE * EMB];
__device__ float g_vn [NGRAPH * EMB];
__device__ float g_vt [NGRAPH * EMB];
// CSR scratch
__device__ int g_deg [MAXN];
__device__ int g_off [MAXN + 1];
__device__ int g_cur [MAXN];
__device__ int g_part[256];
__device__ int g_eids[MAXE];
__device__ int g_ssrc[MAXE];

// ---------------- helpers ----------------
__device__ __forceinline__ void red_add_v4(float* p, float4 v) {
    asm volatile("red.global.add.v4.f32 [%0], {%1,%2,%3,%4};"
                 :: "l"(p), "f"(v.x), "f"(v.y), "f"(v.z), "f"(v.w) : "memory");
}
__device__ __forceinline__ void mma_tf32(float* c, const unsigned* a, unsigned b0, unsigned b1) {
    asm volatile("mma.sync.aligned.m16n8k8.row.col.f32.tf32.tf32.f32 "
                 "{%0,%1,%2,%3},{%4,%5,%6,%7},{%8,%9},{%0,%1,%2,%3};"
                 : "+f"(c[0]), "+f"(c[1]), "+f"(c[2]), "+f"(c[3])
                 : "r"(a[0]), "r"(a[1]), "r"(a[2]), "r"(a[3]), "r"(b0), "r"(b1));
}
__device__ __forceinline__ void cp_async16(float* smem, const float* gmem) {
    unsigned s = (unsigned)__cvta_generic_to_shared(smem);
    asm volatile("cp.async.cg.shared.global [%0], [%1], 16;" :: "r"(s), "l"(gmem));
}
#define CP_COMMIT() asm volatile("cp.async.commit_group;")
#define CP_WAIT1()  asm volatile("cp.async.wait_group 1;")
#define CP_WAIT0()  asm volatile("cp.async.wait_group 0;")

// ================= CSR build (once per launch) =================
__global__ void k_count(const int* __restrict__ eidx, int* __restrict__ deg, int E) {
    int e = blockIdx.x * blockDim.x + threadIdx.x;
    if (e < E) atomicAdd(&deg[eidx[E + e]], 1);
}

__global__ void k_scan1(const int* __restrict__ deg, int* __restrict__ off,
                        int* __restrict__ part, int N) {
    __shared__ int wsum[16];
    int i = blockIdx.x * 512 + threadIdx.x;
    int lane = threadIdx.x & 31, w = threadIdx.x >> 5;
    int v = (i < N) ? deg[i] : 0;
    int x = v;
#pragma unroll
    for (int d = 1; d < 32; d <<= 1) { int y = __shfl_up_sync(0xffffffffu, x, d); if (lane >= d) x += y; }
    if (lane == 31) wsum[w] = x;
    __syncthreads();
    if (w == 0) {
        int s = (lane < 16) ? wsum[lane] : 0;
#pragma unroll
        for (int d = 1; d < 16; d <<= 1) { int y = __shfl_up_sync(0xffffffffu, s, d); if (lane >= d) s += y; }
        if (lane < 16) wsum[lane] = s;
    }
    __syncthreads();
    int base = (w > 0) ? wsum[w - 1] : 0;
    if (i < N) off[i] = base + x - v;
    if (threadIdx.x == 0) part[blockIdx.x] = wsum[15];
}

__global__ void k_scan2(int* __restrict__ part) {
    __shared__ int wsum[8];
    int tid = threadIdx.x;
    int lane = tid & 31, w = tid >> 5;
    int v = part[tid];
    int x = v;
#pragma unroll
    for (int d = 1; d < 32; d <<= 1) { int y = __shfl_up_sync(0xffffffffu, x, d); if (lane >= d) x += y; }
    if (lane == 31) wsum[w] = x;
    __syncthreads();
    if (w == 0) {
        int s = (lane < 8) ? wsum[lane] : 0;
#pragma unroll
        for (int d = 1; d < 8; d <<= 1) { int y = __shfl_up_sync(0xffffffffu, s, d); if (lane >= d) s += y; }
        if (lane < 8) wsum[lane] = s;
    }
    __syncthreads();
    int base = (w > 0) ? wsum[w - 1] : 0;
    part[tid] = base + x - v;
}

__global__ void k_scan3(int* __restrict__ off, int* __restrict__ cur,
                        const int* __restrict__ part, int N, int E) {
    int i = blockIdx.x * 512 + threadIdx.x;
    if (i < N) {
        int o = off[i] + part[blockIdx.x];
        off[i] = o;
        cur[i] = o;
    }
    if (i == 0) off[N] = E;
}

__global__ void k_scatter(const int* __restrict__ eidx, int* __restrict__ cur,
                          int* __restrict__ eids, int* __restrict__ ssrc, int E) {
    int e = blockIdx.x * blockDim.x + threadIdx.x;
    if (e < E) {
        int pos = atomicAdd(&cur[eidx[E + e]], 1);
        eids[pos] = e;
        ssrc[pos] = eidx[e];
    }
}

// ---------------- kernel 0: init vn ----------------
__global__ void k_init_vn(const float* __restrict__ vn_emb, float* __restrict__ vn) {
    int i = blockIdx.x * blockDim.x + threadIdx.x;
    if (i < NGRAPH * EMB) vn[i] = vn_emb[i & (EMB - 1)];
}

// ---------------- kernel 1: hin = h + vn[batch]; vt += segsum(hin) (layer 0) ----------------
__global__ void k_hin_vt(const float* __restrict__ h, const int* __restrict__ batch,
                         const float* __restrict__ vn, float* __restrict__ hin,
                         float* __restrict__ vt, int N) {
    int lane = threadIdx.x;
    int row  = threadIdx.y;
    int base = blockIdx.x * 64;
    float4 acc = make_float4(0.f, 0.f, 0.f, 0.f);
    int gcur = -1;
    for (int it = 0; it < 8; it++) {
        int i = base + it * 8 + row;
        if (i >= N) break;
        int g = batch[i];
        const float4 hv = *(const float4*)&h[(size_t)i * EMB + lane * 4];
        const float4 vv = *(const float4*)&vn[(size_t)g * EMB + lane * 4];
        float4 s = make_float4(hv.x + vv.x, hv.y + vv.y, hv.z + vv.z, hv.w + vv.w);
        *(float4*)&hin[(size_t)i * EMB + lane * 4] = s;
        if (g != gcur) {
            if (gcur >= 0) red_add_v4(&vt[(size_t)gcur * EMB + lane * 4], acc);
            acc = make_float4(0.f, 0.f, 0.f, 0.f);
            gcur = g;
        }
        acc.x += s.x; acc.y += s.y; acc.z += s.z; acc.w += s.w;
    }
    if (gcur >= 0) red_add_v4(&vt[(size_t)gcur * EMB + lane * 4], acc);
}

// ---------------- kernel 1b: vt += segsum(hin) ----------------
__global__ void k_vt(const float* __restrict__ hin, const int* __restrict__ batch,
                     float* __restrict__ vt, int N) {
    int lane = threadIdx.x;
    int row  = threadIdx.y;
    int base = blockIdx.x * 64;
    float4 acc = make_float4(0.f, 0.f, 0.f, 0.f);
    int gcur = -1;
    for (int it = 0; it < 8; it++) {
        int i = base + it * 8 + row;
        if (i >= N) break;
        int g = batch[i];
        const float4 s = *(const float4*)&hin[(size_t)i * EMB + lane * 4];
        if (g != gcur) {
            if (gcur >= 0) red_add_v4(&vt[(size_t)gcur * EMB + lane * 4], acc);
            acc = make_float4(0.f, 0.f, 0.f, 0.f);
            gcur = g;
        }
        acc.x += s.x; acc.y += s.y; acc.z += s.z; acc.w += s.w;
    }
    if (gcur >= 0) red_add_v4(&vt[(size_t)gcur * EMB + lane * 4], acc);
}

// ---------------- kernel 2a: edge embedding GEMM (tensor core, CSR-ordered) ----------------
// 128 edges per CTA (2 tiles of 64), sW staged once. emb[pos] = bf16(ea[eids[pos]] @ We + be)
#define AS_STR 20
#define WE_STR 136

__global__ __launch_bounds__(256) void k_edge_emb(
    const float* __restrict__ ea, const int* __restrict__ eids,
    const float* __restrict__ We, const float* __restrict__ be,
    __nv_bfloat16* __restrict__ emb, int E) {
    __shared__ float As[64 * AS_STR];
    __shared__ float sW[EDIM * WE_STR];

    int tid = threadIdx.x;
    int wid = tid >> 5, lane = tid & 31;
    int g = lane >> 2, t = lane & 3;
    int warp_m = wid >> 2;
    int warp_n = wid & 3;

    // stage We once per CTA
#pragma unroll
    for (int p = 0; p < 8; p++) {
        int li = tid + p * 256;
        int k = li >> 7, c = li & 127;
        sW[k * WE_STR + c] = We[k * EMB + c];
    }

#pragma unroll
    for (int tile = 0; tile < 2; tile++) {
        long long base = (long long)blockIdx.x * 128 + tile * 64;
        if (base >= E) break;

        __syncthreads();   // protect As from previous tile consumers (also covers sW stage)
        {
            int row = tid >> 2, cg = tid & 3;
            long long pos = base + row;
            float4 v = make_float4(0.f, 0.f, 0.f, 0.f);
            if (pos < E) {
                int eid = eids[pos];
                v = *(const float4*)&ea[(size_t)eid * EDIM + cg * 4];
            }
            float* d = &As[row * AS_STR + cg * 4];
            d[0] = v.x; d[1] = v.y; d[2] = v.z; d[3] = v.w;
        }
        __syncthreads();

        float c[2][4][4];
#pragma unroll
        for (int mt = 0; mt < 2; mt++)
#pragma unroll
            for (int nt = 0; nt < 4; nt++)
#pragma unroll
                for (int j = 0; j < 4; j++) c[mt][nt][j] = 0.f;

#pragma unroll
        for (int ks = 0; ks < 2; ks++) {
            int kl = ks * 8;
            unsigned a[2][4];
#pragma unroll
            for (int mt = 0; mt < 2; mt++) {
                int r = warp_m * 32 + mt * 16 + g;
                a[mt][0] = __float_as_uint(As[r * AS_STR + kl + t]);
                a[mt][1] = __float_as_uint(As[(r + 8) * AS_STR + kl + t]);
                a[mt][2] = __float_as_uint(As[r * AS_STR + kl + t + 4]);
                a[mt][3] = __float_as_uint(As[(r + 8) * AS_STR + kl + t + 4]);
            }
#pragma unroll
            for (int nt = 0; nt < 4; nt++) {
                int col = warp_n * 32 + nt * 8 + g;
                unsigned b0 = __float_as_uint(sW[(kl + t) * WE_STR + col]);
                unsigned b1r = __float_as_uint(sW[(kl + t + 4) * WE_STR + col]);
                mma_tf32(c[0][nt], a[0], b0, b1r);
                mma_tf32(c[1][nt], a[1], b0, b1r);
            }
        }

#pragma unroll
        for (int nt = 0; nt < 4; nt++) {
            int col = warp_n * 32 + nt * 8 + t * 2;
            float bv0 = __ldg(&be[col]), bv1 = __ldg(&be[col + 1]);
#pragma unroll
            for (int mt = 0; mt < 2; mt++) {
#pragma unroll
                for (int half = 0; half < 2; half++) {
                    int row = warp_m * 32 + mt * 16 + g + half * 8;
                    long long pos = base + row;
                    if (pos < E) {
                        __nv_bfloat162 o = __floats2bfloat162_rn(
                            c[mt][nt][half * 2] + bv0, c[mt][nt][half * 2 + 1] + bv1);
                        *(__nv_bfloat162*)&emb[(size_t)pos * EMB + col] = o;
                    }
                }
            }
        }
    }
}

// ---------------- kernel 2b: slim CSR aggregation (4-edge unrolled) ----------------
// x(bf16) = hin[node] + sum_p relu(hin[ssrc[p]] + emb[p])
__global__ __launch_bounds__(256) void k_agg_csr(
    const float* __restrict__ hin, const __nv_bfloat16* __restrict__ emb,
    const int* __restrict__ ssrc, const int* __restrict__ off,
    __nv_bfloat16* __restrict__ xout, int N) {
    int tid = threadIdx.x;
    int lane = tid & 31;
    int node = blockIdx.x * 8 + (tid >> 5);
    if (node >= N) return;
    int beg = off[node], end = off[node + 1];

    float4 hn = *(const float4*)&hin[(size_t)node * EMB + lane * 4];
    float4 acc = make_float4(0.f, 0.f, 0.f, 0.f);
    int p = beg;

    for (; p + 4 <= end; p += 4) {
        int s0 = ssrc[p], s1 = ssrc[p + 1], s2 = ssrc[p + 2], s3 = ssrc[p + 3];
        uint2 u0 = *(const uint2*)&emb[(size_t)p * EMB + lane * 4];
        uint2 u1 = *(const uint2*)&emb[(size_t)(p + 1) * EMB + lane * 4];
        uint2 u2 = *(const uint2*)&emb[(size_t)(p + 2) * EMB + lane * 4];
        uint2 u3 = *(const uint2*)&emb[(size_t)(p + 3) * EMB + lane * 4];
        float4 x0 = *(const float4*)&hin[(size_t)s0 * EMB + lane * 4];
        float4 x1 = *(const float4*)&hin[(size_t)s1 * EMB + lane * 4];
        float4 x2 = *(const float4*)&hin[(size_t)s2 * EMB + lane * 4];
        float4 x3 = *(const float4*)&hin[(size_t)s3 * EMB + lane * 4];
        acc.x += fmaxf(x0.x + __uint_as_float(u0.x << 16), 0.f)
               + fmaxf(x1.x + __uint_as_float(u1.x << 16), 0.f)
               + fmaxf(x2.x + __uint_as_float(u2.x << 16), 0.f)
               + fmaxf(x3.x + __uint_as_float(u3.x << 16), 0.f);
        acc.y += fmaxf(x0.y + __uint_as_float(u0.x & 0xFFFF0000u), 0.f)
               + fmaxf(x1.y + __uint_as_float(u1.x & 0xFFFF0000u), 0.f)
               + fmaxf(x2.y + __uint_as_float(u2.x & 0xFFFF0000u), 0.f)
               + fmaxf(x3.y + __uint_as_float(u3.x & 0xFFFF0000u), 0.f);
        acc.z += fmaxf(x0.z + __uint_as_float(u0.y << 16), 0.f)
               + fmaxf(x1.z + __uint_as_float(u1.y << 16), 0.f)
               + fmaxf(x2.z + __uint_as_float(u2.y << 16), 0.f)
               + fmaxf(x3.z + __uint_as_float(u3.y << 16), 0.f);
        acc.w += fmaxf(x0.w + __uint_as_float(u0.y & 0xFFFF0000u), 0.f)
               + fmaxf(x1.w + __uint_as_float(u1.y & 0xFFFF0000u), 0.f)
               + fmaxf(x2.w + __uint_as_float(u2.y & 0xFFFF0000u), 0.f)
               + fmaxf(x3.w + __uint_as_float(u3.y & 0xFFFF0000u), 0.f);
    }
    for (; p + 2 <= end; p += 2) {
        int s0 = ssrc[p], s1 = ssrc[p + 1];
        uint2 u0 = *(const uint2*)&emb[(size_t)p * EMB + lane * 4];
        uint2 u1 = *(const uint2*)&emb[(size_t)(p + 1) * EMB + lane * 4];
        float4 x0 = *(const float4*)&hin[(size_t)s0 * EMB + lane * 4];
        float4 x1 = *(const float4*)&hin[(size_t)s1 * EMB + lane * 4];
        acc.x += fmaxf(x0.x + __uint_as_float(u0.x << 16), 0.f)
               + fmaxf(x1.x + __uint_as_float(u1.x << 16), 0.f);
        acc.y += fmaxf(x0.y + __uint_as_float(u0.x & 0xFFFF0000u), 0.f)
               + fmaxf(x1.y + __uint_as_float(u1.x & 0xFFFF0000u), 0.f);
        acc.z += fmaxf(x0.z + __uint_as_float(u0.y << 16), 0.f)
               + fmaxf(x1.z + __uint_as_float(u1.y << 16), 0.f);
        acc.w += fmaxf(x0.w + __uint_as_float(u0.y & 0xFFFF0000u), 0.f)
               + fmaxf(x1.w + __uint_as_float(u1.y & 0xFFFF0000u), 0.f);
    }
    if (p < end) {
        int s0 = ssrc[p];
        uint2 u0 = *(const uint2*)&emb[(size_t)p * EMB + lane * 4];
        float4 x0 = *(const float4*)&hin[(size_t)s0 * EMB + lane * 4];
        acc.x += fmaxf(x0.x + __uint_as_float(u0.x << 16), 0.f);
        acc.y += fmaxf(x0.y + __uint_as_float(u0.x & 0xFFFF0000u), 0.f);
        acc.z += fmaxf(x0.z + __uint_as_float(u0.y << 16), 0.f);
        acc.w += fmaxf(x0.w + __uint_as_float(u0.y & 0xFFFF0000u), 0.f);
    }
    acc.x += hn.x; acc.y += hn.y; acc.z += hn.z; acc.w += hn.w;
    __nv_bfloat162 p0 = __floats2bfloat162_rn(acc.x, acc.y);
    __nv_bfloat162 p1 = __floats2bfloat162_rn(acc.z, acc.w);
    uint2 o;
    o.x = *(unsigned*)&p0;
    o.y = *(unsigned*)&p1;
    *(uint2*)&xout[(size_t)node * EMB + lane * 4] = o;
}

// ---------------- kernel 3: tensor-core node MLP (tf32, cp.async, occ=2, fused hin_next) ----------------
#define XS_STR 132
#define HS_STR 260
#define W1_STR 264
#define W2_STR 136
#define UB_FLOATS (64 * HS_STR)
#define WD_FLOATS (2 * 32 * W2_STR)
#define MLP_SMEM_FLOATS (UB_FLOATS + WD_FLOATS)

__global__ __launch_bounds__(256, 2) void k_node_mlp(
    const __nv_bfloat16* __restrict__ xin, const float* __restrict__ hin,
    const float* __restrict__ W1, const float* __restrict__ b1,
    const float* __restrict__ W2, const float* __restrict__ b2,
    const float* __restrict__ gamma, const float* __restrict__ beta,
    float* __restrict__ out, const float* __restrict__ vnn,
    const int* __restrict__ batch, int N, int mode, float inv) {
    extern __shared__ float smf[];
    float* Xs = smf;
    float* Hs = smf;
    float* Wd = smf + UB_FLOATS;

    int tid = threadIdx.x;
    int wid = tid >> 5, lane = tid & 31;
    int g = lane >> 2, t = lane & 3;
    int warp_m = wid >> 2;
    int warp_n = wid & 3;
    int base = blockIdx.x * 64;

#pragma unroll
    for (int p = 0; p < 8; p++) {
        int li = tid + p * 256;
        int row = li >> 5;
        int c4 = (li & 31) * 4;
        int node = base + row;
        float4 v = make_float4(0.f, 0.f, 0.f, 0.f);
        if (node < N) {
            uint2 u = *(const uint2*)&xin[(size_t)node * EMB + c4];
            v.x = __uint_as_float(u.x << 16);
            v.y = __uint_as_float(u.x & 0xFFFF0000u);
            v.z = __uint_as_float(u.y << 16);
            v.w = __uint_as_float(u.y & 0xFFFF0000u);
        }
        *(float4*)&Xs[row * XS_STR + c4] = v;
    }

    float c1[2][8][4];
#pragma unroll
    for (int mt = 0; mt < 2; mt++)
#pragma unroll
        for (int nt = 0; nt < 8; nt++)
#pragma unroll
            for (int j = 0; j < 4; j++) c1[mt][nt][j] = 0.f;

    {
#pragma unroll
        for (int p = 0; p < 4; p++) {
            int idx4 = tid + p * 256;
            int row = idx4 >> 6, c4 = idx4 & 63;
            cp_async16(&Wd[row * W1_STR + c4 * 4], &W1[(size_t)row * 256 + c4 * 4]);
        }
        CP_COMMIT();
    }

    for (int kc = 0; kc < 8; kc++) {
        if (kc < 7) {
            float* db = Wd + ((kc + 1) & 1) * (16 * W1_STR);
#pragma unroll
            for (int p = 0; p < 4; p++) {
                int idx4 = tid + p * 256;
                int row = idx4 >> 6, c4 = idx4 & 63;
                cp_async16(&db[row * W1_STR + c4 * 4],
                           &W1[(size_t)((kc + 1) * 16 + row) * 256 + c4 * 4]);
            }
            CP_COMMIT();
            CP_WAIT1();
        } else {
            CP_WAIT0();
        }
        __syncthreads();
        const float* Wb = Wd + (kc & 1) * (16 * W1_STR);
#pragma unroll
        for (int ks = 0; ks < 2; ks++) {
            int kl = ks * 8;
            int kg = kc * 16 + kl;
            unsigned a[2][4];
#pragma unroll
            for (int mt = 0; mt < 2; mt++) {
                int r = warp_m * 32 + mt * 16 + g;
                const float* x0 = &Xs[r * XS_STR + kg + t];
                const float* x8 = &Xs[(r + 8) * XS_STR + kg + t];
                a[mt][0] = __float_as_uint(x0[0]);
                a[mt][1] = __float_as_uint(x8[0]);
                a[mt][2] = __float_as_uint(x0[4]);
                a[mt][3] = __float_as_uint(x8[4]);
            }
#pragma unroll
            for (int nt = 0; nt < 8; nt++) {
                int col = warp_n * 64 + nt * 8 + g;
                unsigned b0 = __float_as_uint(Wb[(kl + t) * W1_STR + col]);
                unsigned b1r = __float_as_uint(Wb[(kl + t + 4) * W1_STR + col]);
                mma_tf32(c1[0][nt], a[0], b0, b1r);
                mma_tf32(c1[1][nt], a[1], b0, b1r);
            }
        }
        __syncthreads();
    }

#pragma unroll
    for (int nt = 0; nt < 8; nt++) {
        int c0 = warp_n * 64 + nt * 8 + t * 2;
        float bb0 = __ldg(&b1[c0]);
        float bb1 = __ldg(&b1[c0 + 1]);
#pragma unroll
        for (int mt = 0; mt < 2; mt++) {
            int r = warp_m * 32 + mt * 16 + g;
            Hs[r * HS_STR + c0]           = fmaxf(c1[mt][nt][0] + bb0, 0.f);
            Hs[r * HS_STR + c0 + 1]       = fmaxf(c1[mt][nt][1] + bb1, 0.f);
            Hs[(r + 8) * HS_STR + c0]     = fmaxf(c1[mt][nt][2] + bb0, 0.f);
            Hs[(r + 8) * HS_STR + c0 + 1] = fmaxf(c1[mt][nt][3] + bb1, 0.f);
        }
    }

    float c2[2][4][4];
#pragma unroll
    for (int mt = 0; mt < 2; mt++)
#pragma unroll
        for (int nt = 0; nt < 4; nt++)
#pragma unroll
            for (int j = 0; j < 4; j++) c2[mt][nt][j] = 0.f;

    {
#pragma unroll
        for (int p = 0; p < 4; p++) {
            int idx4 = tid + p * 256;
            int row = idx4 >> 5, c4 = idx4 & 31;
            cp_async16(&Wd[row * W2_STR + c4 * 4], &W2[(size_t)row * 128 + c4 * 4]);
        }
        CP_COMMIT();
    }

    for (int kc = 0; kc < 8; kc++) {
        if (kc < 7) {
            float* db = Wd + ((kc + 1) & 1) * (32 * W2_STR);
#pragma unroll
            for (int p = 0; p < 4; p++) {
                int idx4 = tid + p * 256;
                int row = idx4 >> 5, c4 = idx4 & 31;
                cp_async16(&db[row * W2_STR + c4 * 4],
                           &W2[(size_t)((kc + 1) * 32 + row) * 128 + c4 * 4]);
            }
            CP_COMMIT();
            CP_WAIT1();
        } else {
            CP_WAIT0();
        }
        __syncthreads();
        const float* Wb = Wd + (kc & 1) * (32 * W2_STR);
#pragma unroll
        for (int ks = 0; ks < 4; ks++) {
            int kl = ks * 8;
            int kg = kc * 32 + kl;
            unsigned a[2][4];
#pragma unroll
            for (int mt = 0; mt < 2; mt++) {
                int r = warp_m * 32 + mt * 16 + g;
                const float* x0 = &Hs[r * HS_STR + kg + t];
                const float* x8 = &Hs[(r + 8) * HS_STR + kg + t];
                a[mt][0] = __float_as_uint(x0[0]);
                a[mt][1] = __float_as_uint(x8[0]);
                a[mt][2] = __float_as_uint(x0[4]);
                a[mt][3] = __float_as_uint(x8[4]);
            }
#pragma unroll
            for (int nt = 0; nt < 4; nt++) {
                int col = warp_n * 32 + nt * 8 + g;
                unsigned b0 = __float_as_uint(Wb[(kl + t) * W2_STR + col]);
                unsigned b1r = __float_as_uint(Wb[(kl + t + 4) * W2_STR + col]);
                mma_tf32(c2[0][nt], a[0], b0, b1r);
                mma_tf32(c2[1][nt], a[1], b0, b1r);
            }
        }
        __syncthreads();
    }

    int bg[2][2];
    if (mode) {
#pragma unroll
        for (int mt = 0; mt < 2; mt++)
#pragma unroll
            for (int half = 0; half < 2; half++) {
                int node = base + warp_m * 32 + mt * 16 + g + half * 8;
                bg[mt][half] = (node < N) ? batch[node] : 0;
            }
    }
#pragma unroll
    for (int nt = 0; nt < 4; nt++) {
        int col = warp_n * 32 + nt * 8 + t * 2;
        float bv0 = __ldg(&b2[col]),          bv1 = __ldg(&b2[col + 1]);
        float gv0 = __ldg(&gamma[col]) * inv, gv1 = __ldg(&gamma[col + 1]) * inv;
        float ev0 = __ldg(&beta[col]),        ev1 = __ldg(&beta[col + 1]);
#pragma unroll
        for (int mt = 0; mt < 2; mt++) {
#pragma unroll
            for (int half = 0; half < 2; half++) {
                int row = warp_m * 32 + mt * 16 + g + half * 8;
                int node = base + row;
                if (node < N) {
                    float z0 = c2[mt][nt][half * 2]     + bv0;
                    float z1 = c2[mt][nt][half * 2 + 1] + bv1;
                    z0 = z0 * gv0 + ev0;
                    z1 = z1 * gv1 + ev1;
                    if (mode) { z0 = fmaxf(z0, 0.f); z1 = fmaxf(z1, 0.f); }
                    float2 hr = *(const float2*)&hin[(size_t)node * EMB + col];
                    z0 += hr.x; z1 += hr.y;
                    if (mode) {
                        float2 vv = *(const float2*)&vnn[(size_t)bg[mt][half] * EMB + col];
                        z0 += vv.x; z1 += vv.y;
                    }
                    *(float2*)&out[(size_t)node * EMB + col] = make_float2(z0, z1);
                }
            }
        }
    }
}

// ---------------- kernel 4: virtual-node MLP ----------------
__global__ __launch_bounds__(256) void k_vn_mlp(
    const float* __restrict__ vt, float* __restrict__ vn,
    const float* __restrict__ w1, const float* __restrict__ b1,
    const float* __restrict__ g1, const float* __restrict__ be1,
    const float* __restrict__ w2, const float* __restrict__ b2,
    const float* __restrict__ g2, const float* __restrict__ be2, float inv) {
    __shared__ float sv[EMB];
    __shared__ float sm1[HID];
    int g = blockIdx.x;
    int tid = threadIdx.x;
    if (tid < EMB) sv[tid] = vt[(size_t)g * EMB + tid] + vn[(size_t)g * EMB + tid];
    __syncthreads();
    {
        int j = tid;
        float s = b1[j];
#pragma unroll 8
        for (int k = 0; k < EMB; k++) s += sv[k] * w1[(size_t)k * HID + j];
        s = s * (g1[j] * inv) + be1[j];
        sm1[j] = fmaxf(s, 0.f);
    }
    __syncthreads();
    if (tid < EMB) {
        int c = tid;
        float s = b2[c];
#pragma unroll 8
        for (int j = 0; j < HID; j++) s += sm1[j] * w2[(size_t)j * EMB + c];
        s = s * (g2[c] * inv) + be2[c];
        vn[(size_t)g * EMB + c] += fmaxf(s, 0.f);
    }
}

// ---------------- host orchestration ----------------
extern "C" void kernel_launch(void* const* d_in, const int* in_sizes, int n_in,
                              void* d_out, int out_size) {
    if (n_in < 21) return;

    const float* input_feature = (const float*)d_in[0];
    const int* edge_index;
    const float* edge_attr;
    long long E;
    if ((long long)in_sizes[1] < (long long)in_sizes[2]) {
        edge_index = (const int*)d_in[1];
        edge_attr  = (const float*)d_in[2];
        E = in_sizes[1] / 2;
    } else {
        edge_index = (const int*)d_in[2];
        edge_attr  = (const float*)d_in[1];
        E = in_sizes[2] / 2;
    }
    const int* batch = (const int*)d_in[3];
    int N = in_sizes[0] / EMB;

    const float* vn_emb = (const float*)d_in[4];
    const float* cew = (const float*)d_in[5];
    const float* ceb = (const float*)d_in[6];
    const float* cw1 = (const float*)d_in[7];
    const float* cb1 = (const float*)d_in[8];
    const float* cw2 = (const float*)d_in[9];
    const float* cb2 = (const float*)d_in[10];
    const float* bng = (const float*)d_in[11];
    const float* bnb = (const float*)d_in[12];
    const float* vw1 = (const float*)d_in[13];
    const float* vb1 = (const float*)d_in[14];
    const float* vg1 = (const float*)d_in[15];
    const float* vbe1 = (const float*)d_in[16];
    const float* vw2 = (const float*)d_in[17];
    const float* vb2 = (const float*)d_in[18];
    const float* vg2 = (const float*)d_in[19];
    const float* vbe2 = (const float*)d_in[20];

    float *hinA, *hinB, *vn, *vt;
    __nv_bfloat16 *xbuf, *embbuf;
    int *deg, *off, *cur, *part, *eids, *ssrc;
    cudaGetSymbolAddress((void**)&hinA, g_hinA);
    cudaGetSymbolAddress((void**)&hinB, g_hinB);
    cudaGetSymbolAddress((void**)&xbuf, g_x);
    cudaGetSymbolAddress((void**)&embbuf, g_emb);
    cudaGetSymbolAddress((void**)&vn, g_vn);
    cudaGetSymbolAddress((void**)&vt, g_vt);
    cudaGetSymbolAddress((void**)&deg, g_deg);
    cudaGetSymbolAddress((void**)&off, g_off);
    cudaGetSymbolAddress((void**)&cur, g_cur);
    cudaGetSymbolAddress((void**)&part, g_part);
    cudaGetSymbolAddress((void**)&eids, g_eids);
    cudaGetSymbolAddress((void**)&ssrc, g_ssrc);

    cudaFuncSetAttribute(k_node_mlp, cudaFuncAttributeMaxDynamicSharedMemorySize,
                         MLP_SMEM_FLOATS * (int)sizeof(float));

    const float inv = 1.0f / sqrtf(1.0f + 1e-5f);

    // ---- CSR build ----
    int NB = (N + 511) / 512;
    cudaMemsetAsync(deg, 0, (size_t)N * sizeof(int));
    cudaMemsetAsync(part, 0, 256 * sizeof(int));
    k_count<<<(int)((E + 255) / 256), 256>>>(edge_index, deg, (int)E);
    k_scan1<<<NB, 512>>>(deg, off, part, N);
    k_scan2<<<1, 256>>>(part);
    k_scan3<<<NB, 512>>>(off, cur, part, N, (int)E);
    k_scatter<<<(int)((E + 255) / 256), 256>>>(edge_index, cur, eids, ssrc, (int)E);

    k_init_vn<<<(NGRAPH * EMB + 255) / 256, 256>>>(vn_emb, vn);

    int nblk = (N + 63) / 64;
    int ablk = (N + 7) / 8;
    int emblk = (int)((E + 127) / 128);
    size_t mlp_smem = MLP_SMEM_FLOATS * sizeof(float);

    cudaMemsetAsync(vt, 0, (size_t)NGRAPH * EMB * sizeof(float));
    k_hin_vt<<<nblk, dim3(32, 8)>>>(input_feature, batch, vn, hinA, vt, N);

    float* hin_cur = hinA;
    float* hin_nxt = hinB;
    for (int l = 0; l < NLAYER; l++) {
        int last = (l == NLAYER - 1);

        k_edge_emb<<<emblk, 256>>>(edge_attr, eids,
                                   cew + (size_t)l * EDIM * EMB, ceb + (size_t)l * EMB,
                                   embbuf, (int)E);

        k_agg_csr<<<ablk, 256>>>(hin_cur, embbuf, ssrc, off, xbuf, N);

        if (!last) {
            k_vn_mlp<<<NGRAPH, 256>>>(vt, vn,
                                      vw1 + (size_t)l * EMB * HID, vb1 + (size_t)l * HID,
                                      vg1 + (size_t)l * HID, vbe1 + (size_t)l * HID,
                                      vw2 + (size_t)l * HID * EMB, vb2 + (size_t)l * EMB,
                                      vg2 + (size_t)l * EMB, vbe2 + (size_t)l * EMB, inv);
        }

        float* outp = last ? (float*)d_out : hin_nxt;
        k_node_mlp<<<nblk, 256, mlp_smem>>>(
            xbuf, hin_cur,
            cw1 + (size_t)l * EMB * HID, cb1 + (size_t)l * HID,
            cw2 + (size_t)l * HID * EMB, cb2 + (size_t)l * EMB,
            bng + (size_t)l * EMB, bnb + (size_t)l * EMB,
            outp, vn, batch, N, last ? 0 : 1, inv);

        if (l == 0) {
            cudaMemsetAsync(vt, 0, (size_t)NGRAPH * EMB * sizeof(float));
            k_vt<<<nblk, dim3(32, 8)>>>(hin_nxt, batch, vt, N);
        }

        float* tmp = hin_cur; hin_cur = hin_nxt; hin_nxt = tmp;
    }
}

// round 14
// speedup vs baseline: 1.3444x; 1.0243x over previous
#include <cuda_runtime.h>
#include <cuda_bf16.h>
#include <math.h>

// ---------------- problem constants ----------------
#define EMB 128
#define HID 256
#define EDIM 16
#define NGRAPH 512
#define NLAYER 3
#define MAXN 100352
#define MAXE 600064

// ---------------- scratch (device globals) ----------------
__device__ float g_hinA[(size_t)MAXN * EMB];
__device__ float g_hinB[(size_t)MAXN * EMB];
__device__ __nv_bfloat16 g_x[(size_t)MAXN * EMB];
__device__ __nv_bfloat16 g_emb[(size_t)MAXE * EMB];
__device__ float g_vn [NGRAPH * EMB];
__device__ float g_vt [NGRAPH * EMB];
// CSR scratch
__device__ int g_deg [MAXN];
__device__ int g_off [MAXN + 1];
__device__ int g_cur [MAXN];
__device__ int g_part[256];
__device__ int g_eids[MAXE];
__device__ int g_ssrc[MAXE];

// ---------------- helpers ----------------
__device__ __forceinline__ void red_add_v4(float* p, float4 v) {
    asm volatile("red.global.add.v4.f32 [%0], {%1,%2,%3,%4};"
                 :: "l"(p), "f"(v.x), "f"(v.y), "f"(v.z), "f"(v.w) : "memory");
}
__device__ __forceinline__ void mma_tf32(float* c, const unsigned* a, unsigned b0, unsigned b1) {
    asm volatile("mma.sync.aligned.m16n8k8.row.col.f32.tf32.tf32.f32 "
                 "{%0,%1,%2,%3},{%4,%5,%6,%7},{%8,%9},{%0,%1,%2,%3};"
                 : "+f"(c[0]), "+f"(c[1]), "+f"(c[2]), "+f"(c[3])
                 : "r"(a[0]), "r"(a[1]), "r"(a[2]), "r"(a[3]), "r"(b0), "r"(b1));
}
__device__ __forceinline__ void cp_async16(float* smem, const float* gmem) {
    unsigned s = (unsigned)__cvta_generic_to_shared(smem);
    asm volatile("cp.async.cg.shared.global [%0], [%1], 16;" :: "r"(s), "l"(gmem));
}
#define CP_COMMIT() asm volatile("cp.async.commit_group;")
#define CP_WAIT1()  asm volatile("cp.async.wait_group 1;")
#define CP_WAIT0()  asm volatile("cp.async.wait_group 0;")

// ================= CSR build (once per launch) =================
__global__ void k_count(const int* __restrict__ eidx, int* __restrict__ deg, int E) {
    int e = blockIdx.x * blockDim.x + threadIdx.x;
    if (e < E) atomicAdd(&deg[eidx[E + e]], 1);
}

__global__ void k_scan1(const int* __restrict__ deg, int* __restrict__ off,
                        int* __restrict__ part, int N) {
    __shared__ int wsum[16];
    int i = blockIdx.x * 512 + threadIdx.x;
    int lane = threadIdx.x & 31, w = threadIdx.x >> 5;
    int v = (i < N) ? deg[i] : 0;
    int x = v;
#pragma unroll
    for (int d = 1; d < 32; d <<= 1) { int y = __shfl_up_sync(0xffffffffu, x, d); if (lane >= d) x += y; }
    if (lane == 31) wsum[w] = x;
    __syncthreads();
    if (w == 0) {
        int s = (lane < 16) ? wsum[lane] : 0;
#pragma unroll
        for (int d = 1; d < 16; d <<= 1) { int y = __shfl_up_sync(0xffffffffu, s, d); if (lane >= d) s += y; }
        if (lane < 16) wsum[lane] = s;
    }
    __syncthreads();
    int base = (w > 0) ? wsum[w - 1] : 0;
    if (i < N) off[i] = base + x - v;
    if (threadIdx.x == 0) part[blockIdx.x] = wsum[15];
}

__global__ void k_scan2(int* __restrict__ part) {
    __shared__ int wsum[8];
    int tid = threadIdx.x;
    int lane = tid & 31, w = tid >> 5;
    int v = part[tid];
    int x = v;
#pragma unroll
    for (int d = 1; d < 32; d <<= 1) { int y = __shfl_up_sync(0xffffffffu, x, d); if (lane >= d) x += y; }
    if (lane == 31) wsum[w] = x;
    __syncthreads();
    if (w == 0) {
        int s = (lane < 8) ? wsum[lane] : 0;
#pragma unroll
        for (int d = 1; d < 8; d <<= 1) { int y = __shfl_up_sync(0xffffffffu, s, d); if (lane >= d) s += y; }
        if (lane < 8) wsum[lane] = s;
    }
    __syncthreads();
    int base = (w > 0) ? wsum[w - 1] : 0;
    part[tid] = base + x - v;
}

__global__ void k_scan3(int* __restrict__ off, int* __restrict__ cur,
                        const int* __restrict__ part, int N, int E) {
    int i = blockIdx.x * 512 + threadIdx.x;
    if (i < N) {
        int o = off[i] + part[blockIdx.x];
        off[i] = o;
        cur[i] = o;
    }
    if (i == 0) off[N] = E;
}

__global__ void k_scatter(const int* __restrict__ eidx, int* __restrict__ cur,
                          int* __restrict__ eids, int* __restrict__ ssrc, int E) {
    int e = blockIdx.x * blockDim.x + threadIdx.x;
    if (e < E) {
        int pos = atomicAdd(&cur[eidx[E + e]], 1);
        eids[pos] = e;
        ssrc[pos] = eidx[e];
    }
}

// ---------------- kernel 0: init vn ----------------
__global__ void k_init_vn(const float* __restrict__ vn_emb, float* __restrict__ vn) {
    int i = blockIdx.x * blockDim.x + threadIdx.x;
    if (i < NGRAPH * EMB) vn[i] = vn_emb[i & (EMB - 1)];
}

// ---------------- kernel 1: hin = h + vn[batch]; vt += segsum(hin) (layer 0) ----------------
__global__ void k_hin_vt(const float* __restrict__ h, const int* __restrict__ batch,
                         const float* __restrict__ vn, float* __restrict__ hin,
                         float* __restrict__ vt, int N) {
    int lane = threadIdx.x;
    int row  = threadIdx.y;
    int base = blockIdx.x * 64;
    float4 acc = make_float4(0.f, 0.f, 0.f, 0.f);
    int gcur = -1;
    for (int it = 0; it < 8; it++) {
        int i = base + it * 8 + row;
        if (i >= N) break;
        int g = batch[i];
        const float4 hv = *(const float4*)&h[(size_t)i * EMB + lane * 4];
        const float4 vv = *(const float4*)&vn[(size_t)g * EMB + lane * 4];
        float4 s = make_float4(hv.x + vv.x, hv.y + vv.y, hv.z + vv.z, hv.w + vv.w);
        *(float4*)&hin[(size_t)i * EMB + lane * 4] = s;
        if (g != gcur) {
            if (gcur >= 0) red_add_v4(&vt[(size_t)gcur * EMB + lane * 4], acc);
            acc = make_float4(0.f, 0.f, 0.f, 0.f);
            gcur = g;
        }
        acc.x += s.x; acc.y += s.y; acc.z += s.z; acc.w += s.w;
    }
    if (gcur >= 0) red_add_v4(&vt[(size_t)gcur * EMB + lane * 4], acc);
}

// ---------------- kernel 2a: edge embedding GEMM (tensor core, CSR-ordered) ----------------
// emb[pos][:] = bf16(ea[eids[pos]] @ We + be), 64 edges per CTA (256 thr, 8 warps 2m x 4n)
#define AS_STR 20
#define WE_STR 136

__global__ __launch_bounds__(256) void k_edge_emb(
    const float* __restrict__ ea, const int* __restrict__ eids,
    const float* __restrict__ We, const float* __restrict__ be,
    __nv_bfloat16* __restrict__ emb, int E) {
    __shared__ float As[64 * AS_STR];
    __shared__ float sW[EDIM * WE_STR];

    int tid = threadIdx.x;
    int wid = tid >> 5, lane = tid & 31;
    int g = lane >> 2, t = lane & 3;
    int warp_m = wid >> 2;   // 0..1
    int warp_n = wid & 3;    // 0..3
    long long base = (long long)blockIdx.x * 64;

#pragma unroll
    for (int p = 0; p < 8; p++) {
        int li = tid + p * 256;
        int k = li >> 7, c = li & 127;
        sW[k * WE_STR + c] = We[k * EMB + c];
    }
    {
        int row = tid >> 2, cg = tid & 3;
        long long pos = base + row;
        float4 v = make_float4(0.f, 0.f, 0.f, 0.f);
        if (pos < E) {
            int eid = eids[pos];
            v = *(const float4*)&ea[(size_t)eid * EDIM + cg * 4];
        }
        float* d = &As[row * AS_STR + cg * 4];
        d[0] = v.x; d[1] = v.y; d[2] = v.z; d[3] = v.w;
    }
    __syncthreads();

    float c[2][4][4];
#pragma unroll
    for (int mt = 0; mt < 2; mt++)
#pragma unroll
        for (int nt = 0; nt < 4; nt++)
#pragma unroll
            for (int j = 0; j < 4; j++) c[mt][nt][j] = 0.f;

#pragma unroll
    for (int ks = 0; ks < 2; ks++) {
        int kl = ks * 8;
        unsigned a[2][4];
#pragma unroll
        for (int mt = 0; mt < 2; mt++) {
            int r = warp_m * 32 + mt * 16 + g;
            a[mt][0] = __float_as_uint(As[r * AS_STR + kl + t]);
            a[mt][1] = __float_as_uint(As[(r + 8) * AS_STR + kl + t]);
            a[mt][2] = __float_as_uint(As[r * AS_STR + kl + t + 4]);
            a[mt][3] = __float_as_uint(As[(r + 8) * AS_STR + kl + t + 4]);
        }
#pragma unroll
        for (int nt = 0; nt < 4; nt++) {
            int col = warp_n * 32 + nt * 8 + g;
            unsigned b0 = __float_as_uint(sW[(kl + t) * WE_STR + col]);
            unsigned b1r = __float_as_uint(sW[(kl + t + 4) * WE_STR + col]);
            mma_tf32(c[0][nt], a[0], b0, b1r);
            mma_tf32(c[1][nt], a[1], b0, b1r);
        }
    }

#pragma unroll
    for (int nt = 0; nt < 4; nt++) {
        int col = warp_n * 32 + nt * 8 + t * 2;
        float bv0 = __ldg(&be[col]), bv1 = __ldg(&be[col + 1]);
#pragma unroll
        for (int mt = 0; mt < 2; mt++) {
#pragma unroll
            for (int half = 0; half < 2; half++) {
                int row = warp_m * 32 + mt * 16 + g + half * 8;
                long long pos = base + row;
                if (pos < E) {
                    __nv_bfloat162 o = __floats2bfloat162_rn(
                        c[mt][nt][half * 2] + bv0, c[mt][nt][half * 2 + 1] + bv1);
                    *(__nv_bfloat162*)&emb[(size_t)pos * EMB + col] = o;
                }
            }
        }
    }
}

// ---------------- kernel 2b: slim CSR aggregation (2-unrolled, R11 form) ----------------
// x(bf16) = hin[node] + sum_p relu(hin[ssrc[p]] + emb[p]); optional vt += hn (segsum fusion)
__global__ __launch_bounds__(256) void k_agg_csr(
    const float* __restrict__ hin, const __nv_bfloat16* __restrict__ emb,
    const int* __restrict__ ssrc, const int* __restrict__ off,
    __nv_bfloat16* __restrict__ xout, const int* __restrict__ batch,
    float* __restrict__ vt, int N, int doVT) {
    int tid = threadIdx.x;
    int lane = tid & 31;
    int node = blockIdx.x * 8 + (tid >> 5);
    if (node >= N) return;
    int beg = off[node], end = off[node + 1];

    float4 hn = *(const float4*)&hin[(size_t)node * EMB + lane * 4];
    if (doVT) {
        int g = batch[node];
        red_add_v4(&vt[(size_t)g * EMB + lane * 4], hn);
    }
    float4 acc = make_float4(0.f, 0.f, 0.f, 0.f);
    int p = beg;

    for (; p + 2 <= end; p += 2) {
        int s0 = ssrc[p], s1 = ssrc[p + 1];
        uint2 u0 = *(const uint2*)&emb[(size_t)p * EMB + lane * 4];
        uint2 u1 = *(const uint2*)&emb[(size_t)(p + 1) * EMB + lane * 4];
        float4 x0 = *(const float4*)&hin[(size_t)s0 * EMB + lane * 4];
        float4 x1 = *(const float4*)&hin[(size_t)s1 * EMB + lane * 4];
        acc.x += fmaxf(x0.x + __uint_as_float(u0.x << 16), 0.f)
               + fmaxf(x1.x + __uint_as_float(u1.x << 16), 0.f);
        acc.y += fmaxf(x0.y + __uint_as_float(u0.x & 0xFFFF0000u), 0.f)
               + fmaxf(x1.y + __uint_as_float(u1.x & 0xFFFF0000u), 0.f);
        acc.z += fmaxf(x0.z + __uint_as_float(u0.y << 16), 0.f)
               + fmaxf(x1.z + __uint_as_float(u1.y << 16), 0.f);
        acc.w += fmaxf(x0.w + __uint_as_float(u0.y & 0xFFFF0000u), 0.f)
               + fmaxf(x1.w + __uint_as_float(u1.y & 0xFFFF0000u), 0.f);
    }
    if (p < end) {
        int s0 = ssrc[p];
        uint2 u0 = *(const uint2*)&emb[(size_t)p * EMB + lane * 4];
        float4 x0 = *(const float4*)&hin[(size_t)s0 * EMB + lane * 4];
        acc.x += fmaxf(x0.x + __uint_as_float(u0.x << 16), 0.f);
        acc.y += fmaxf(x0.y + __uint_as_float(u0.x & 0xFFFF0000u), 0.f);
        acc.z += fmaxf(x0.z + __uint_as_float(u0.y << 16), 0.f);
        acc.w += fmaxf(x0.w + __uint_as_float(u0.y & 0xFFFF0000u), 0.f);
    }
    acc.x += hn.x; acc.y += hn.y; acc.z += hn.z; acc.w += hn.w;
    __nv_bfloat162 p0 = __floats2bfloat162_rn(acc.x, acc.y);
    __nv_bfloat162 p1 = __floats2bfloat162_rn(acc.z, acc.w);
    uint2 o;
    o.x = *(unsigned*)&p0;
    o.y = *(unsigned*)&p1;
    *(uint2*)&xout[(size_t)node * EMB + lane * 4] = o;
}

// ---------------- kernel 3: tensor-core node MLP (tf32, cp.async, occ=2, fused hin_next) ----------------
#define XS_STR 132
#define HS_STR 260
#define W1_STR 264
#define W2_STR 136
#define UB_FLOATS (64 * HS_STR)
#define WD_FLOATS (2 * 32 * W2_STR)
#define MLP_SMEM_FLOATS (UB_FLOATS + WD_FLOATS)

__global__ __launch_bounds__(256, 2) void k_node_mlp(
    const __nv_bfloat16* __restrict__ xin, const float* __restrict__ hin,
    const float* __restrict__ W1, const float* __restrict__ b1,
    const float* __restrict__ W2, const float* __restrict__ b2,
    const float* __restrict__ gamma, const float* __restrict__ beta,
    float* __restrict__ out, const float* __restrict__ vnn,
    const int* __restrict__ batch, int N, int mode, float inv) {
    extern __shared__ float smf[];
    float* Xs = smf;
    float* Hs = smf;
    float* Wd = smf + UB_FLOATS;

    int tid = threadIdx.x;
    int wid = tid >> 5, lane = tid & 31;
    int g = lane >> 2, t = lane & 3;
    int warp_m = wid >> 2;
    int warp_n = wid & 3;
    int base = blockIdx.x * 64;

#pragma unroll
    for (int p = 0; p < 8; p++) {
        int li = tid + p * 256;
        int row = li >> 5;
        int c4 = (li & 31) * 4;
        int node = base + row;
        float4 v = make_float4(0.f, 0.f, 0.f, 0.f);
        if (node < N) {
            uint2 u = *(const uint2*)&xin[(size_t)node * EMB + c4];
            v.x = __uint_as_float(u.x << 16);
            v.y = __uint_as_float(u.x & 0xFFFF0000u);
            v.z = __uint_as_float(u.y << 16);
            v.w = __uint_as_float(u.y & 0xFFFF0000u);
        }
        *(float4*)&Xs[row * XS_STR + c4] = v;
    }

    float c1[2][8][4];
#pragma unroll
    for (int mt = 0; mt < 2; mt++)
#pragma unroll
        for (int nt = 0; nt < 8; nt++)
#pragma unroll
            for (int j = 0; j < 4; j++) c1[mt][nt][j] = 0.f;

    {
#pragma unroll
        for (int p = 0; p < 4; p++) {
            int idx4 = tid + p * 256;
            int row = idx4 >> 6, c4 = idx4 & 63;
            cp_async16(&Wd[row * W1_STR + c4 * 4], &W1[(size_t)row * 256 + c4 * 4]);
        }
        CP_COMMIT();
    }

    for (int kc = 0; kc < 8; kc++) {
        if (kc < 7) {
            float* db = Wd + ((kc + 1) & 1) * (16 * W1_STR);
#pragma unroll
            for (int p = 0; p < 4; p++) {
                int idx4 = tid + p * 256;
                int row = idx4 >> 6, c4 = idx4 & 63;
                cp_async16(&db[row * W1_STR + c4 * 4],
                           &W1[(size_t)((kc + 1) * 16 + row) * 256 + c4 * 4]);
            }
            CP_COMMIT();
            CP_WAIT1();
        } else {
            CP_WAIT0();
        }
        __syncthreads();
        const float* Wb = Wd + (kc & 1) * (16 * W1_STR);
#pragma unroll
        for (int ks = 0; ks < 2; ks++) {
            int kl = ks * 8;
            int kg = kc * 16 + kl;
            unsigned a[2][4];
#pragma unroll
            for (int mt = 0; mt < 2; mt++) {
                int r = warp_m * 32 + mt * 16 + g;
                const float* x0 = &Xs[r * XS_STR + kg + t];
                const float* x8 = &Xs[(r + 8) * XS_STR + kg + t];
                a[mt][0] = __float_as_uint(x0[0]);
                a[mt][1] = __float_as_uint(x8[0]);
                a[mt][2] = __float_as_uint(x0[4]);
                a[mt][3] = __float_as_uint(x8[4]);
            }
#pragma unroll
            for (int nt = 0; nt < 8; nt++) {
                int col = warp_n * 64 + nt * 8 + g;
                unsigned b0 = __float_as_uint(Wb[(kl + t) * W1_STR + col]);
                unsigned b1r = __float_as_uint(Wb[(kl + t + 4) * W1_STR + col]);
                mma_tf32(c1[0][nt], a[0], b0, b1r);
                mma_tf32(c1[1][nt], a[1], b0, b1r);
            }
        }
        __syncthreads();
    }

#pragma unroll
    for (int nt = 0; nt < 8; nt++) {
        int c0 = warp_n * 64 + nt * 8 + t * 2;
        float bb0 = __ldg(&b1[c0]);
        float bb1 = __ldg(&b1[c0 + 1]);
#pragma unroll
        for (int mt = 0; mt < 2; mt++) {
            int r = warp_m * 32 + mt * 16 + g;
            Hs[r * HS_STR + c0]           = fmaxf(c1[mt][nt][0] + bb0, 0.f);
            Hs[r * HS_STR + c0 + 1]       = fmaxf(c1[mt][nt][1] + bb1, 0.f);
            Hs[(r + 8) * HS_STR + c0]     = fmaxf(c1[mt][nt][2] + bb0, 0.f);
            Hs[(r + 8) * HS_STR + c0 + 1] = fmaxf(c1[mt][nt][3] + bb1, 0.f);
        }
    }

    float c2[2][4][4];
#pragma unroll
    for (int mt = 0; mt < 2; mt++)
#pragma unroll
        for (int nt = 0; nt < 4; nt++)
#pragma unroll
            for (int j = 0; j < 4; j++) c2[mt][nt][j] = 0.f;

    {
#pragma unroll
        for (int p = 0; p < 4; p++) {
            int idx4 = tid + p * 256;
            int row = idx4 >> 5, c4 = idx4 & 31;
            cp_async16(&Wd[row * W2_STR + c4 * 4], &W2[(size_t)row * 128 + c4 * 4]);
        }
        CP_COMMIT();
    }

    for (int kc = 0; kc < 8; kc++) {
        if (kc < 7) {
            float* db = Wd + ((kc + 1) & 1) * (32 * W2_STR);
#pragma unroll
            for (int p = 0; p < 4; p++) {
                int idx4 = tid + p * 256;
                int row = idx4 >> 5, c4 = idx4 & 31;
                cp_async16(&db[row * W2_STR + c4 * 4],
                           &W2[(size_t)((kc + 1) * 32 + row) * 128 + c4 * 4]);
            }
            CP_COMMIT();
            CP_WAIT1();
        } else {
            CP_WAIT0();
        }
        __syncthreads();
        const float* Wb = Wd + (kc & 1) * (32 * W2_STR);
#pragma unroll
        for (int ks = 0; ks < 4; ks++) {
            int kl = ks * 8;
            int kg = kc * 32 + kl;
            unsigned a[2][4];
#pragma unroll
            for (int mt = 0; mt < 2; mt++) {
                int r = warp_m * 32 + mt * 16 + g;
                const float* x0 = &Hs[r * HS_STR + kg + t];
                const float* x8 = &Hs[(r + 8) * HS_STR + kg + t];
                a[mt][0] = __float_as_uint(x0[0]);
                a[mt][1] = __float_as_uint(x8[0]);
                a[mt][2] = __float_as_uint(x0[4]);
                a[mt][3] = __float_as_uint(x8[4]);
            }
#pragma unroll
            for (int nt = 0; nt < 4; nt++) {
                int col = warp_n * 32 + nt * 8 + g;
                unsigned b0 = __float_as_uint(Wb[(kl + t) * W2_STR + col]);
                unsigned b1r = __float_as_uint(Wb[(kl + t + 4) * W2_STR + col]);
                mma_tf32(c2[0][nt], a[0], b0, b1r);
                mma_tf32(c2[1][nt], a[1], b0, b1r);
            }
        }
        __syncthreads();
    }

    int bg[2][2];
    if (mode) {
#pragma unroll
        for (int mt = 0; mt < 2; mt++)
#pragma unroll
            for (int half = 0; half < 2; half++) {
                int node = base + warp_m * 32 + mt * 16 + g + half * 8;
                bg[mt][half] = (node < N) ? batch[node] : 0;
            }
    }
#pragma unroll
    for (int nt = 0; nt < 4; nt++) {
        int col = warp_n * 32 + nt * 8 + t * 2;
        float bv0 = __ldg(&b2[col]),          bv1 = __ldg(&b2[col + 1]);
        float gv0 = __ldg(&gamma[col]) * inv, gv1 = __ldg(&gamma[col + 1]) * inv;
        float ev0 = __ldg(&beta[col]),        ev1 = __ldg(&beta[col + 1]);
#pragma unroll
        for (int mt = 0; mt < 2; mt++) {
#pragma unroll
            for (int half = 0; half < 2; half++) {
                int row = warp_m * 32 + mt * 16 + g + half * 8;
                int node = base + row;
                if (node < N) {
                    float z0 = c2[mt][nt][half * 2]     + bv0;
                    float z1 = c2[mt][nt][half * 2 + 1] + bv1;
                    z0 = z0 * gv0 + ev0;
                    z1 = z1 * gv1 + ev1;
                    if (mode) { z0 = fmaxf(z0, 0.f); z1 = fmaxf(z1, 0.f); }
                    float2 hr = *(const float2*)&hin[(size_t)node * EMB + col];
                    z0 += hr.x; z1 += hr.y;
                    if (mode) {
                        float2 vv = *(const float2*)&vnn[(size_t)bg[mt][half] * EMB + col];
                        z0 += vv.x; z1 += vv.y;
                    }
                    *(float2*)&out[(size_t)node * EMB + col] = make_float2(z0, z1);
                }
            }
        }
    }
}

// ---------------- kernel 4: virtual-node MLP ----------------
__global__ __launch_bounds__(256) void k_vn_mlp(
    const float* __restrict__ vt, float* __restrict__ vn,
    const float* __restrict__ w1, const float* __restrict__ b1,
    const float* __restrict__ g1, const float* __restrict__ be1,
    const float* __restrict__ w2, const float* __restrict__ b2,
    const float* __restrict__ g2, const float* __restrict__ be2, float inv) {
    __shared__ float sv[EMB];
    __shared__ float sm1[HID];
    int g = blockIdx.x;
    int tid = threadIdx.x;
    if (tid < EMB) sv[tid] = vt[(size_t)g * EMB + tid] + vn[(size_t)g * EMB + tid];
    __syncthreads();
    {
        int j = tid;
        float s = b1[j];
#pragma unroll 8
        for (int k = 0; k < EMB; k++) s += sv[k] * w1[(size_t)k * HID + j];
        s = s * (g1[j] * inv) + be1[j];
        sm1[j] = fmaxf(s, 0.f);
    }
    __syncthreads();
    if (tid < EMB) {
        int c = tid;
        float s = b2[c];
#pragma unroll 8
        for (int j = 0; j < HID; j++) s += sm1[j] * w2[(size_t)j * EMB + c];
        s = s * (g2[c] * inv) + be2[c];
        vn[(size_t)g * EMB + c] += fmaxf(s, 0.f);
    }
}

// ---------------- host orchestration ----------------
extern "C" void kernel_launch(void* const* d_in, const int* in_sizes, int n_in,
                              void* d_out, int out_size) {
    if (n_in < 21) return;

    const float* input_feature = (const float*)d_in[0];
    const int* edge_index;
    const float* edge_attr;
    long long E;
    if ((long long)in_sizes[1] < (long long)in_sizes[2]) {
        edge_index = (const int*)d_in[1];
        edge_attr  = (const float*)d_in[2];
        E = in_sizes[1] / 2;
    } else {
        edge_index = (const int*)d_in[2];
        edge_attr  = (const float*)d_in[1];
        E = in_sizes[2] / 2;
    }
    const int* batch = (const int*)d_in[3];
    int N = in_sizes[0] / EMB;

    const float* vn_emb = (const float*)d_in[4];
    const float* cew = (const float*)d_in[5];
    const float* ceb = (const float*)d_in[6];
    const float* cw1 = (const float*)d_in[7];
    const float* cb1 = (const float*)d_in[8];
    const float* cw2 = (const float*)d_in[9];
    const float* cb2 = (const float*)d_in[10];
    const float* bng = (const float*)d_in[11];
    const float* bnb = (const float*)d_in[12];
    const float* vw1 = (const float*)d_in[13];
    const float* vb1 = (const float*)d_in[14];
    const float* vg1 = (const float*)d_in[15];
    const float* vbe1 = (const float*)d_in[16];
    const float* vw2 = (const float*)d_in[17];
    const float* vb2 = (const float*)d_in[18];
    const float* vg2 = (const float*)d_in[19];
    const float* vbe2 = (const float*)d_in[20];

    float *hinA, *hinB, *vn, *vt;
    __nv_bfloat16 *xbuf, *embbuf;
    int *deg, *off, *cur, *part, *eids, *ssrc;
    cudaGetSymbolAddress((void**)&hinA, g_hinA);
    cudaGetSymbolAddress((void**)&hinB, g_hinB);
    cudaGetSymbolAddress((void**)&xbuf, g_x);
    cudaGetSymbolAddress((void**)&embbuf, g_emb);
    cudaGetSymbolAddress((void**)&vn, g_vn);
    cudaGetSymbolAddress((void**)&vt, g_vt);
    cudaGetSymbolAddress((void**)&deg, g_deg);
    cudaGetSymbolAddress((void**)&off, g_off);
    cudaGetSymbolAddress((void**)&cur, g_cur);
    cudaGetSymbolAddress((void**)&part, g_part);
    cudaGetSymbolAddress((void**)&eids, g_eids);
    cudaGetSymbolAddress((void**)&ssrc, g_ssrc);

    cudaFuncSetAttribute(k_node_mlp, cudaFuncAttributeMaxDynamicSharedMemorySize,
                         MLP_SMEM_FLOATS * (int)sizeof(float));

    const float inv = 1.0f / sqrtf(1.0f + 1e-5f);

    // ---- CSR build ----
    int NB = (N + 511) / 512;
    cudaMemsetAsync(deg, 0, (size_t)N * sizeof(int));
    cudaMemsetAsync(part, 0, 256 * sizeof(int));
    k_count<<<(int)((E + 255) / 256), 256>>>(edge_index, deg, (int)E);
    k_scan1<<<NB, 512>>>(deg, off, part, N);
    k_scan2<<<1, 256>>>(part);
    k_scan3<<<NB, 512>>>(off, cur, part, N, (int)E);
    k_scatter<<<(int)((E + 255) / 256), 256>>>(edge_index, cur, eids, ssrc, (int)E);

    k_init_vn<<<(NGRAPH * EMB + 255) / 256, 256>>>(vn_emb, vn);

    int nblk = (N + 63) / 64;
    int ablk = (N + 7) / 8;
    int emblk = (int)((E + 63) / 64);
    size_t mlp_smem = MLP_SMEM_FLOATS * sizeof(float);

    cudaMemsetAsync(vt, 0, (size_t)NGRAPH * EMB * sizeof(float));
    k_hin_vt<<<nblk, dim3(32, 8)>>>(input_feature, batch, vn, hinA, vt, N);

    float* hin_cur = hinA;
    float* hin_nxt = hinB;
    for (int l = 0; l < NLAYER; l++) {
        int last = (l == NLAYER - 1);

        k_edge_emb<<<emblk, 256>>>(edge_attr, eids,
                                   cew + (size_t)l * EDIM * EMB, ceb + (size_t)l * EMB,
                                   embbuf, (int)E);

        // layer 1's agg also accumulates vt1 = segsum(hin1) (vt zeroed after vn_mlp(0))
        k_agg_csr<<<ablk, 256>>>(hin_cur, embbuf, ssrc, off, xbuf,
                                 batch, vt, N, (l == 1) ? 1 : 0);

        if (!last) {
            k_vn_mlp<<<NGRAPH, 256>>>(vt, vn,
                                      vw1 + (size_t)l * EMB * HID, vb1 + (size_t)l * HID,
                                      vg1 + (size_t)l * HID, vbe1 + (size_t)l * HID,
                                      vw2 + (size_t)l * HID * EMB, vb2 + (size_t)l * EMB,
                                      vg2 + (size_t)l * EMB, vbe2 + (size_t)l * EMB, inv);
            if (l == 0) {
                // vt consumed by vn_mlp(0); clear for layer-1 agg's segsum fusion
                cudaMemsetAsync(vt, 0, (size_t)NGRAPH * EMB * sizeof(float));
            }
        }

        float* outp = last ? (float*)d_out : hin_nxt;
        k_node_mlp<<<nblk, 256, mlp_smem>>>(
            xbuf, hin_cur,
            cw1 + (size_t)l * EMB * HID, cb1 + (size_t)l * HID,
            cw2 + (size_t)l * HID * EMB, cb2 + (size_t)l * EMB,
            bng + (size_t)l * EMB, bnb + (size_t)l * EMB,
            outp, vn, batch, N, last ? 0 : 1, inv);

        float* tmp = hin_cur; hin_cur = hin_nxt; hin_nxt = tmp;
    }
}

// round 15
// speedup vs baseline: 1.3459x; 1.0011x over previous
#include <cuda_runtime.h>
#include <cuda_bf16.h>
#include <math.h>

// ---------------- problem constants ----------------
#define EMB 128
#define HID 256
#define EDIM 16
#define NGRAPH 512
#define NLAYER 3
#define MAXN 100352
#define MAXE 600064

// ---------------- scratch (device globals) ----------------
__device__ float g_hinA[(size_t)MAXN * EMB];
__device__ float g_hinB[(size_t)MAXN * EMB];
__device__ __nv_bfloat16 g_x[(size_t)MAXN * EMB];
__device__ __nv_bfloat16 g_emb[(size_t)MAXE * EMB];
__device__ float g_vn [NGRAPH * EMB];
__device__ float g_vt [NGRAPH * EMB];
// CSR scratch
__device__ int g_deg [MAXN];
__device__ int g_off [MAXN + 1];
__device__ int g_cur [MAXN];
__device__ int g_part[256];
__device__ int g_eids[MAXE];
__device__ int g_ssrc[MAXE];

// ---------------- helpers ----------------
__device__ __forceinline__ void red_add_v4(float* p, float4 v) {
    asm volatile("red.global.add.v4.f32 [%0], {%1,%2,%3,%4};"
                 :: "l"(p), "f"(v.x), "f"(v.y), "f"(v.z), "f"(v.w) : "memory");
}
__device__ __forceinline__ void red_add_v2(float* p, float2 v) {
    asm volatile("red.global.add.v2.f32 [%0], {%1,%2};"
                 :: "l"(p), "f"(v.x), "f"(v.y) : "memory");
}
__device__ __forceinline__ void mma_tf32(float* c, const unsigned* a, unsigned b0, unsigned b1) {
    asm volatile("mma.sync.aligned.m16n8k8.row.col.f32.tf32.tf32.f32 "
                 "{%0,%1,%2,%3},{%4,%5,%6,%7},{%8,%9},{%0,%1,%2,%3};"
                 : "+f"(c[0]), "+f"(c[1]), "+f"(c[2]), "+f"(c[3])
                 : "r"(a[0]), "r"(a[1]), "r"(a[2]), "r"(a[3]), "r"(b0), "r"(b1));
}
__device__ __forceinline__ void cp_async16(float* smem, const float* gmem) {
    unsigned s = (unsigned)__cvta_generic_to_shared(smem);
    asm volatile("cp.async.cg.shared.global [%0], [%1], 16;" :: "r"(s), "l"(gmem));
}
#define CP_COMMIT() asm volatile("cp.async.commit_group;")
#define CP_WAIT1()  asm volatile("cp.async.wait_group 1;")
#define CP_WAIT0()  asm volatile("cp.async.wait_group 0;")

// ================= CSR build (once per launch) =================
__global__ void k_count(const int* __restrict__ eidx, int* __restrict__ deg, int E) {
    int e = blockIdx.x * blockDim.x + threadIdx.x;
    if (e < E) atomicAdd(&deg[eidx[E + e]], 1);
}

__global__ void k_scan1(const int* __restrict__ deg, int* __restrict__ off,
                        int* __restrict__ part, int N) {
    __shared__ int wsum[16];
    int i = blockIdx.x * 512 + threadIdx.x;
    int lane = threadIdx.x & 31, w = threadIdx.x >> 5;
    int v = (i < N) ? deg[i] : 0;
    int x = v;
#pragma unroll
    for (int d = 1; d < 32; d <<= 1) { int y = __shfl_up_sync(0xffffffffu, x, d); if (lane >= d) x += y; }
    if (lane == 31) wsum[w] = x;
    __syncthreads();
    if (w == 0) {
        int s = (lane < 16) ? wsum[lane] : 0;
#pragma unroll
        for (int d = 1; d < 16; d <<= 1) { int y = __shfl_up_sync(0xffffffffu, s, d); if (lane >= d) s += y; }
        if (lane < 16) wsum[lane] = s;
    }
    __syncthreads();
    int base = (w > 0) ? wsum[w - 1] : 0;
    if (i < N) off[i] = base + x - v;
    if (threadIdx.x == 0) part[blockIdx.x] = wsum[15];
}

__global__ void k_scan2(int* __restrict__ part) {
    __shared__ int wsum[8];
    int tid = threadIdx.x;
    int lane = tid & 31, w = tid >> 5;
    int v = part[tid];
    int x = v;
#pragma unroll
    for (int d = 1; d < 32; d <<= 1) { int y = __shfl_up_sync(0xffffffffu, x, d); if (lane >= d) x += y; }
    if (lane == 31) wsum[w] = x;
    __syncthreads();
    if (w == 0) {
        int s = (lane < 8) ? wsum[lane] : 0;
#pragma unroll
        for (int d = 1; d < 8; d <<= 1) { int y = __shfl_up_sync(0xffffffffu, s, d); if (lane >= d) s += y; }
        if (lane < 8) wsum[lane] = s;
    }
    __syncthreads();
    int base = (w > 0) ? wsum[w - 1] : 0;
    part[tid] = base + x - v;
}

__global__ void k_scan3(int* __restrict__ off, int* __restrict__ cur,
                        const int* __restrict__ part, int N, int E) {
    int i = blockIdx.x * 512 + threadIdx.x;
    if (i < N) {
        int o = off[i] + part[blockIdx.x];
        off[i] = o;
        cur[i] = o;
    }
    if (i == 0) off[N] = E;
}

__global__ void k_scatter(const int* __restrict__ eidx, int* __restrict__ cur,
                          int* __restrict__ eids, int* __restrict__ ssrc, int E) {
    int e = blockIdx.x * blockDim.x + threadIdx.x;
    if (e < E) {
        int pos = atomicAdd(&cur[eidx[E + e]], 1);
        eids[pos] = e;
        ssrc[pos] = eidx[e];
    }
}

// ---------------- kernel 0: init vn ----------------
__global__ void k_init_vn(const float* __restrict__ vn_emb, float* __restrict__ vn) {
    int i = blockIdx.x * blockDim.x + threadIdx.x;
    if (i < NGRAPH * EMB) vn[i] = vn_emb[i & (EMB - 1)];
}

// ---------------- kernel 1: hin = h + vn[batch]; vt += segsum(hin) (layer 0) ----------------
__global__ void k_hin_vt(const float* __restrict__ h, const int* __restrict__ batch,
                         const float* __restrict__ vn, float* __restrict__ hin,
                         float* __restrict__ vt, int N) {
    int lane = threadIdx.x;
    int row  = threadIdx.y;
    int base = blockIdx.x * 64;
    float4 acc = make_float4(0.f, 0.f, 0.f, 0.f);
    int gcur = -1;
    for (int it = 0; it < 8; it++) {
        int i = base + it * 8 + row;
        if (i >= N) break;
        int g = batch[i];
        const float4 hv = *(const float4*)&h[(size_t)i * EMB + lane * 4];
        const float4 vv = *(const float4*)&vn[(size_t)g * EMB + lane * 4];
        float4 s = make_float4(hv.x + vv.x, hv.y + vv.y, hv.z + vv.z, hv.w + vv.w);
        *(float4*)&hin[(size_t)i * EMB + lane * 4] = s;
        if (g != gcur) {
            if (gcur >= 0) red_add_v4(&vt[(size_t)gcur * EMB + lane * 4], acc);
            acc = make_float4(0.f, 0.f, 0.f, 0.f);
            gcur = g;
        }
        acc.x += s.x; acc.y += s.y; acc.z += s.z; acc.w += s.w;
    }
    if (gcur >= 0) red_add_v4(&vt[(size_t)gcur * EMB + lane * 4], acc);
}

// ---------------- kernel 2a: edge embedding GEMM (tensor core, CSR-ordered) ----------------
#define AS_STR 20
#define WE_STR 136

__global__ __launch_bounds__(256) void k_edge_emb(
    const float* __restrict__ ea, const int* __restrict__ eids,
    const float* __restrict__ We, const float* __restrict__ be,
    __nv_bfloat16* __restrict__ emb, int E) {
    __shared__ float As[64 * AS_STR];
    __shared__ float sW[EDIM * WE_STR];

    int tid = threadIdx.x;
    int wid = tid >> 5, lane = tid & 31;
    int g = lane >> 2, t = lane & 3;
    int warp_m = wid >> 2;
    int warp_n = wid & 3;
    long long base = (long long)blockIdx.x * 64;

#pragma unroll
    for (int p = 0; p < 8; p++) {
        int li = tid + p * 256;
        int k = li >> 7, c = li & 127;
        sW[k * WE_STR + c] = We[k * EMB + c];
    }
    {
        int row = tid >> 2, cg = tid & 3;
        long long pos = base + row;
        float4 v = make_float4(0.f, 0.f, 0.f, 0.f);
        if (pos < E) {
            int eid = eids[pos];
            v = *(const float4*)&ea[(size_t)eid * EDIM + cg * 4];
        }
        float* d = &As[row * AS_STR + cg * 4];
        d[0] = v.x; d[1] = v.y; d[2] = v.z; d[3] = v.w;
    }
    __syncthreads();

    float c[2][4][4];
#pragma unroll
    for (int mt = 0; mt < 2; mt++)
#pragma unroll
        for (int nt = 0; nt < 4; nt++)
#pragma unroll
            for (int j = 0; j < 4; j++) c[mt][nt][j] = 0.f;

#pragma unroll
    for (int ks = 0; ks < 2; ks++) {
        int kl = ks * 8;
        unsigned a[2][4];
#pragma unroll
        for (int mt = 0; mt < 2; mt++) {
            int r = warp_m * 32 + mt * 16 + g;
            a[mt][0] = __float_as_uint(As[r * AS_STR + kl + t]);
            a[mt][1] = __float_as_uint(As[(r + 8) * AS_STR + kl + t]);
            a[mt][2] = __float_as_uint(As[r * AS_STR + kl + t + 4]);
            a[mt][3] = __float_as_uint(As[(r + 8) * AS_STR + kl + t + 4]);
        }
#pragma unroll
        for (int nt = 0; nt < 4; nt++) {
            int col = warp_n * 32 + nt * 8 + g;
            unsigned b0 = __float_as_uint(sW[(kl + t) * WE_STR + col]);
            unsigned b1r = __float_as_uint(sW[(kl + t + 4) * WE_STR + col]);
            mma_tf32(c[0][nt], a[0], b0, b1r);
            mma_tf32(c[1][nt], a[1], b0, b1r);
        }
    }

#pragma unroll
    for (int nt = 0; nt < 4; nt++) {
        int col = warp_n * 32 + nt * 8 + t * 2;
        float bv0 = __ldg(&be[col]), bv1 = __ldg(&be[col + 1]);
#pragma unroll
        for (int mt = 0; mt < 2; mt++) {
#pragma unroll
            for (int half = 0; half < 2; half++) {
                int row = warp_m * 32 + mt * 16 + g + half * 8;
                long long pos = base + row;
                if (pos < E) {
                    __nv_bfloat162 o = __floats2bfloat162_rn(
                        c[mt][nt][half * 2] + bv0, c[mt][nt][half * 2 + 1] + bv1);
                    *(__nv_bfloat162*)&emb[(size_t)pos * EMB + col] = o;
                }
            }
        }
    }
}

// ---------------- kernel 2b: slim CSR aggregation (R11 form, untouched) ----------------
__global__ __launch_bounds__(256) void k_agg_csr(
    const float* __restrict__ hin, const __nv_bfloat16* __restrict__ emb,
    const int* __restrict__ ssrc, const int* __restrict__ off,
    __nv_bfloat16* __restrict__ xout, int N) {
    int tid = threadIdx.x;
    int lane = tid & 31;
    int node = blockIdx.x * 8 + (tid >> 5);
    if (node >= N) return;
    int beg = off[node], end = off[node + 1];

    float4 hn = *(const float4*)&hin[(size_t)node * EMB + lane * 4];
    float4 acc = make_float4(0.f, 0.f, 0.f, 0.f);
    int p = beg;

    for (; p + 2 <= end; p += 2) {
        int s0 = ssrc[p], s1 = ssrc[p + 1];
        uint2 u0 = *(const uint2*)&emb[(size_t)p * EMB + lane * 4];
        uint2 u1 = *(const uint2*)&emb[(size_t)(p + 1) * EMB + lane * 4];
        float4 x0 = *(const float4*)&hin[(size_t)s0 * EMB + lane * 4];
        float4 x1 = *(const float4*)&hin[(size_t)s1 * EMB + lane * 4];
        acc.x += fmaxf(x0.x + __uint_as_float(u0.x << 16), 0.f)
               + fmaxf(x1.x + __uint_as_float(u1.x << 16), 0.f);
        acc.y += fmaxf(x0.y + __uint_as_float(u0.x & 0xFFFF0000u), 0.f)
               + fmaxf(x1.y + __uint_as_float(u1.x & 0xFFFF0000u), 0.f);
        acc.z += fmaxf(x0.z + __uint_as_float(u0.y << 16), 0.f)
               + fmaxf(x1.z + __uint_as_float(u1.y << 16), 0.f);
        acc.w += fmaxf(x0.w + __uint_as_float(u0.y & 0xFFFF0000u), 0.f)
               + fmaxf(x1.w + __uint_as_float(u1.y & 0xFFFF0000u), 0.f);
    }
    if (p < end) {
        int s0 = ssrc[p];
        uint2 u0 = *(const uint2*)&emb[(size_t)p * EMB + lane * 4];
        float4 x0 = *(const float4*)&hin[(size_t)s0 * EMB + lane * 4];
        acc.x += fmaxf(x0.x + __uint_as_float(u0.x << 16), 0.f);
        acc.y += fmaxf(x0.y + __uint_as_float(u0.x & 0xFFFF0000u), 0.f);
        acc.z += fmaxf(x0.z + __uint_as_float(u0.y << 16), 0.f);
        acc.w += fmaxf(x0.w + __uint_as_float(u0.y & 0xFFFF0000u), 0.f);
    }
    acc.x += hn.x; acc.y += hn.y; acc.z += hn.z; acc.w += hn.w;
    __nv_bfloat162 p0 = __floats2bfloat162_rn(acc.x, acc.y);
    __nv_bfloat162 p1 = __floats2bfloat162_rn(acc.z, acc.w);
    uint2 o;
    o.x = *(unsigned*)&p0;
    o.y = *(unsigned*)&p1;
    *(uint2*)&xout[(size_t)node * EMB + lane * 4] = o;
}

// ---------------- kernel 3: tensor-core node MLP (tf32, cp.async, occ=2) ----------------
// mode 0: out = BN(z) + hin (-> d_out)
// mode 1: out = relu(BN(z)) + hin + vn_next[batch] (-> hin_next); if doVT, vt += out
#define XS_STR 132
#define HS_STR 260
#define W1_STR 264
#define W2_STR 136
#define UB_FLOATS (64 * HS_STR)
#define WD_FLOATS (2 * 32 * W2_STR)
#define MLP_SMEM_FLOATS (UB_FLOATS + WD_FLOATS)

__global__ __launch_bounds__(256, 2) void k_node_mlp(
    const __nv_bfloat16* __restrict__ xin, const float* __restrict__ hin,
    const float* __restrict__ W1, const float* __restrict__ b1,
    const float* __restrict__ W2, const float* __restrict__ b2,
    const float* __restrict__ gamma, const float* __restrict__ beta,
    float* __restrict__ out, const float* __restrict__ vnn,
    const int* __restrict__ batch, float* __restrict__ vt,
    int N, int mode, int doVT, float inv) {
    extern __shared__ float smf[];
    float* Xs = smf;
    float* Hs = smf;
    float* Wd = smf + UB_FLOATS;

    int tid = threadIdx.x;
    int wid = tid >> 5, lane = tid & 31;
    int g = lane >> 2, t = lane & 3;
    int warp_m = wid >> 2;
    int warp_n = wid & 3;
    int base = blockIdx.x * 64;

#pragma unroll
    for (int p = 0; p < 8; p++) {
        int li = tid + p * 256;
        int row = li >> 5;
        int c4 = (li & 31) * 4;
        int node = base + row;
        float4 v = make_float4(0.f, 0.f, 0.f, 0.f);
        if (node < N) {
            uint2 u = *(const uint2*)&xin[(size_t)node * EMB + c4];
            v.x = __uint_as_float(u.x << 16);
            v.y = __uint_as_float(u.x & 0xFFFF0000u);
            v.z = __uint_as_float(u.y << 16);
            v.w = __uint_as_float(u.y & 0xFFFF0000u);
        }
        *(float4*)&Xs[row * XS_STR + c4] = v;
    }

    float c1[2][8][4];
#pragma unroll
    for (int mt = 0; mt < 2; mt++)
#pragma unroll
        for (int nt = 0; nt < 8; nt++)
#pragma unroll
            for (int j = 0; j < 4; j++) c1[mt][nt][j] = 0.f;

    {
#pragma unroll
        for (int p = 0; p < 4; p++) {
            int idx4 = tid + p * 256;
            int row = idx4 >> 6, c4 = idx4 & 63;
            cp_async16(&Wd[row * W1_STR + c4 * 4], &W1[(size_t)row * 256 + c4 * 4]);
        }
        CP_COMMIT();
    }

    for (int kc = 0; kc < 8; kc++) {
        if (kc < 7) {
            float* db = Wd + ((kc + 1) & 1) * (16 * W1_STR);
#pragma unroll
            for (int p = 0; p < 4; p++) {
                int idx4 = tid + p * 256;
                int row = idx4 >> 6, c4 = idx4 & 63;
                cp_async16(&db[row * W1_STR + c4 * 4],
                           &W1[(size_t)((kc + 1) * 16 + row) * 256 + c4 * 4]);
            }
            CP_COMMIT();
            CP_WAIT1();
        } else {
            CP_WAIT0();
        }
        __syncthreads();
        const float* Wb = Wd + (kc & 1) * (16 * W1_STR);
#pragma unroll
        for (int ks = 0; ks < 2; ks++) {
            int kl = ks * 8;
            int kg = kc * 16 + kl;
            unsigned a[2][4];
#pragma unroll
            for (int mt = 0; mt < 2; mt++) {
                int r = warp_m * 32 + mt * 16 + g;
                const float* x0 = &Xs[r * XS_STR + kg + t];
                const float* x8 = &Xs[(r + 8) * XS_STR + kg + t];
                a[mt][0] = __float_as_uint(x0[0]);
                a[mt][1] = __float_as_uint(x8[0]);
                a[mt][2] = __float_as_uint(x0[4]);
                a[mt][3] = __float_as_uint(x8[4]);
            }
#pragma unroll
            for (int nt = 0; nt < 8; nt++) {
                int col = warp_n * 64 + nt * 8 + g;
                unsigned b0 = __float_as_uint(Wb[(kl + t) * W1_STR + col]);
                unsigned b1r = __float_as_uint(Wb[(kl + t + 4) * W1_STR + col]);
                mma_tf32(c1[0][nt], a[0], b0, b1r);
                mma_tf32(c1[1][nt], a[1], b0, b1r);
            }
        }
        __syncthreads();
    }

#pragma unroll
    for (int nt = 0; nt < 8; nt++) {
        int c0 = warp_n * 64 + nt * 8 + t * 2;
        float bb0 = __ldg(&b1[c0]);
        float bb1 = __ldg(&b1[c0 + 1]);
#pragma unroll
        for (int mt = 0; mt < 2; mt++) {
            int r = warp_m * 32 + mt * 16 + g;
            Hs[r * HS_STR + c0]           = fmaxf(c1[mt][nt][0] + bb0, 0.f);
            Hs[r * HS_STR + c0 + 1]       = fmaxf(c1[mt][nt][1] + bb1, 0.f);
            Hs[(r + 8) * HS_STR + c0]     = fmaxf(c1[mt][nt][2] + bb0, 0.f);
            Hs[(r + 8) * HS_STR + c0 + 1] = fmaxf(c1[mt][nt][3] + bb1, 0.f);
        }
    }

    float c2[2][4][4];
#pragma unroll
    for (int mt = 0; mt < 2; mt++)
#pragma unroll
        for (int nt = 0; nt < 4; nt++)
#pragma unroll
            for (int j = 0; j < 4; j++) c2[mt][nt][j] = 0.f;

    {
#pragma unroll
        for (int p = 0; p < 4; p++) {
            int idx4 = tid + p * 256;
            int row = idx4 >> 5, c4 = idx4 & 31;
            cp_async16(&Wd[row * W2_STR + c4 * 4], &W2[(size_t)row * 128 + c4 * 4]);
        }
        CP_COMMIT();
    }

    for (int kc = 0; kc < 8; kc++) {
        if (kc < 7) {
            float* db = Wd + ((kc + 1) & 1) * (32 * W2_STR);
#pragma unroll
            for (int p = 0; p < 4; p++) {
                int idx4 = tid + p * 256;
                int row = idx4 >> 5, c4 = idx4 & 31;
                cp_async16(&db[row * W2_STR + c4 * 4],
                           &W2[(size_t)((kc + 1) * 32 + row) * 128 + c4 * 4]);
            }
            CP_COMMIT();
            CP_WAIT1();
        } else {
            CP_WAIT0();
        }
        __syncthreads();
        const float* Wb = Wd + (kc & 1) * (32 * W2_STR);
#pragma unroll
        for (int ks = 0; ks < 4; ks++) {
            int kl = ks * 8;
            int kg = kc * 32 + kl;
            unsigned a[2][4];
#pragma unroll
            for (int mt = 0; mt < 2; mt++) {
                int r = warp_m * 32 + mt * 16 + g;
                const float* x0 = &Hs[r * HS_STR + kg + t];
                const float* x8 = &Hs[(r + 8) * HS_STR + kg + t];
                a[mt][0] = __float_as_uint(x0[0]);
                a[mt][1] = __float_as_uint(x8[0]);
                a[mt][2] = __float_as_uint(x0[4]);
                a[mt][3] = __float_as_uint(x8[4]);
            }
#pragma unroll
            for (int nt = 0; nt < 4; nt++) {
                int col = warp_n * 32 + nt * 8 + g;
                unsigned b0 = __float_as_uint(Wb[(kl + t) * W2_STR + col]);
                unsigned b1r = __float_as_uint(Wb[(kl + t + 4) * W2_STR + col]);
                mma_tf32(c2[0][nt], a[0], b0, b1r);
                mma_tf32(c2[1][nt], a[1], b0, b1r);
            }
        }
        __syncthreads();
    }

    int bg[2][2];
    if (mode) {
#pragma unroll
        for (int mt = 0; mt < 2; mt++)
#pragma unroll
            for (int half = 0; half < 2; half++) {
                int node = base + warp_m * 32 + mt * 16 + g + half * 8;
                bg[mt][half] = (node < N) ? batch[node] : 0;
            }
    }
#pragma unroll
    for (int nt = 0; nt < 4; nt++) {
        int col = warp_n * 32 + nt * 8 + t * 2;
        float bv0 = __ldg(&b2[col]),          bv1 = __ldg(&b2[col + 1]);
        float gv0 = __ldg(&gamma[col]) * inv, gv1 = __ldg(&gamma[col + 1]) * inv;
        float ev0 = __ldg(&beta[col]),        ev1 = __ldg(&beta[col + 1]);
#pragma unroll
        for (int mt = 0; mt < 2; mt++) {
#pragma unroll
            for (int half = 0; half < 2; half++) {
                int row = warp_m * 32 + mt * 16 + g + half * 8;
                int node = base + row;
                if (node < N) {
                    float z0 = c2[mt][nt][half * 2]     + bv0;
                    float z1 = c2[mt][nt][half * 2 + 1] + bv1;
                    z0 = z0 * gv0 + ev0;
                    z1 = z1 * gv1 + ev1;
                    if (mode) { z0 = fmaxf(z0, 0.f); z1 = fmaxf(z1, 0.f); }
                    float2 hr = *(const float2*)&hin[(size_t)node * EMB + col];
                    z0 += hr.x; z1 += hr.y;
                    if (mode) {
                        float2 vv = *(const float2*)&vnn[(size_t)bg[mt][half] * EMB + col];
                        z0 += vv.x; z1 += vv.y;
                    }
                    *(float2*)&out[(size_t)node * EMB + col] = make_float2(z0, z1);
                    if (doVT) {
                        // vt_{l+1} += hin_{l+1}[node] (values already in regs)
                        red_add_v2(&vt[(size_t)bg[mt][half] * EMB + col],
                                   make_float2(z0, z1));
                    }
                }
            }
        }
    }
}

// ---------------- kernel 4: virtual-node MLP ----------------
__global__ __launch_bounds__(256) void k_vn_mlp(
    const float* __restrict__ vt, float* __restrict__ vn,
    const float* __restrict__ w1, const float* __restrict__ b1,
    const float* __restrict__ g1, const float* __restrict__ be1,
    const float* __restrict__ w2, const float* __restrict__ b2,
    const float* __restrict__ g2, const float* __restrict__ be2, float inv) {
    __shared__ float sv[EMB];
    __shared__ float sm1[HID];
    int g = blockIdx.x;
    int tid = threadIdx.x;
    if (tid < EMB) sv[tid] = vt[(size_t)g * EMB + tid] + vn[(size_t)g * EMB + tid];
    __syncthreads();
    {
        int j = tid;
        float s = b1[j];
#pragma unroll 8
        for (int k = 0; k < EMB; k++) s += sv[k] * w1[(size_t)k * HID + j];
        s = s * (g1[j] * inv) + be1[j];
        sm1[j] = fmaxf(s, 0.f);
    }
    __syncthreads();
    if (tid < EMB) {
        int c = tid;
        float s = b2[c];
#pragma unroll 8
        for (int j = 0; j < HID; j++) s += sm1[j] * w2[(size_t)j * EMB + c];
        s = s * (g2[c] * inv) + be2[c];
        vn[(size_t)g * EMB + c] += fmaxf(s, 0.f);
    }
}

// ---------------- host orchestration ----------------
extern "C" void kernel_launch(void* const* d_in, const int* in_sizes, int n_in,
                              void* d_out, int out_size) {
    if (n_in < 21) return;

    const float* input_feature = (const float*)d_in[0];
    const int* edge_index;
    const float* edge_attr;
    long long E;
    if ((long long)in_sizes[1] < (long long)in_sizes[2]) {
        edge_index = (const int*)d_in[1];
        edge_attr  = (const float*)d_in[2];
        E = in_sizes[1] / 2;
    } else {
        edge_index = (const int*)d_in[2];
        edge_attr  = (const float*)d_in[1];
        E = in_sizes[2] / 2;
    }
    const int* batch = (const int*)d_in[3];
    int N = in_sizes[0] / EMB;

    const float* vn_emb = (const float*)d_in[4];
    const float* cew = (const float*)d_in[5];
    const float* ceb = (const float*)d_in[6];
    const float* cw1 = (const float*)d_in[7];
    const float* cb1 = (const float*)d_in[8];
    const float* cw2 = (const float*)d_in[9];
    const float* cb2 = (const float*)d_in[10];
    const float* bng = (const float*)d_in[11];
    const float* bnb = (const float*)d_in[12];
    const float* vw1 = (const float*)d_in[13];
    const float* vb1 = (const float*)d_in[14];
    const float* vg1 = (const float*)d_in[15];
    const float* vbe1 = (const float*)d_in[16];
    const float* vw2 = (const float*)d_in[17];
    const float* vb2 = (const float*)d_in[18];
    const float* vg2 = (const float*)d_in[19];
    const float* vbe2 = (const float*)d_in[20];

    float *hinA, *hinB, *vn, *vt;
    __nv_bfloat16 *xbuf, *embbuf;
    int *deg, *off, *cur, *part, *eids, *ssrc;
    cudaGetSymbolAddress((void**)&hinA, g_hinA);
    cudaGetSymbolAddress((void**)&hinB, g_hinB);
    cudaGetSymbolAddress((void**)&xbuf, g_x);
    cudaGetSymbolAddress((void**)&embbuf, g_emb);
    cudaGetSymbolAddress((void**)&vn, g_vn);
    cudaGetSymbolAddress((void**)&vt, g_vt);
    cudaGetSymbolAddress((void**)&deg, g_deg);
    cudaGetSymbolAddress((void**)&off, g_off);
    cudaGetSymbolAddress((void**)&cur, g_cur);
    cudaGetSymbolAddress((void**)&part, g_part);
    cudaGetSymbolAddress((void**)&eids, g_eids);
    cudaGetSymbolAddress((void**)&ssrc, g_ssrc);

    cudaFuncSetAttribute(k_node_mlp, cudaFuncAttributeMaxDynamicSharedMemorySize,
                         MLP_SMEM_FLOATS * (int)sizeof(float));

    const float inv = 1.0f / sqrtf(1.0f + 1e-5f);

    // ---- CSR build ----
    int NB = (N + 511) / 512;
    cudaMemsetAsync(deg, 0, (size_t)N * sizeof(int));
    cudaMemsetAsync(part, 0, 256 * sizeof(int));
    k_count<<<(int)((E + 255) / 256), 256>>>(edge_index, deg, (int)E);
    k_scan1<<<NB, 512>>>(deg, off, part, N);
    k_scan2<<<1, 256>>>(part);
    k_scan3<<<NB, 512>>>(off, cur, part, N, (int)E);
    k_scatter<<<(int)((E + 255) / 256), 256>>>(edge_index, cur, eids, ssrc, (int)E);

    k_init_vn<<<(NGRAPH * EMB + 255) / 256, 256>>>(vn_emb, vn);

    int nblk = (N + 63) / 64;
    int ablk = (N + 7) / 8;
    int emblk = (int)((E + 63) / 64);
    size_t mlp_smem = MLP_SMEM_FLOATS * sizeof(float);

    cudaMemsetAsync(vt, 0, (size_t)NGRAPH * EMB * sizeof(float));
    k_hin_vt<<<nblk, dim3(32, 8)>>>(input_feature, batch, vn, hinA, vt, N);

    float* hin_cur = hinA;
    float* hin_nxt = hinB;
    for (int l = 0; l < NLAYER; l++) {
        int last = (l == NLAYER - 1);

        k_edge_emb<<<emblk, 256>>>(edge_attr, eids,
                                   cew + (size_t)l * EDIM * EMB, ceb + (size_t)l * EMB,
                                   embbuf, (int)E);

        k_agg_csr<<<ablk, 256>>>(hin_cur, embbuf, ssrc, off, xbuf, N);

        if (!last) {
            // vn <- vn_{l+1} consumes vt_l; then clear vt for the fused vt_{l+1} accumulation
            k_vn_mlp<<<NGRAPH, 256>>>(vt, vn,
                                      vw1 + (size_t)l * EMB * HID, vb1 + (size_t)l * HID,
                                      vg1 + (size_t)l * HID, vbe1 + (size_t)l * HID,
                                      vw2 + (size_t)l * HID * EMB, vb2 + (size_t)l * EMB,
                                      vg2 + (size_t)l * EMB, vbe2 + (size_t)l * EMB, inv);
            if (l == 0) cudaMemsetAsync(vt, 0, (size_t)NGRAPH * EMB * sizeof(float));
        }

        float* outp = last ? (float*)d_out : hin_nxt;
        // layer 0's MLP (mode 1) also accumulates vt1 = segsum(hin1) from its epilogue regs
        k_node_mlp<<<nblk, 256, mlp_smem>>>(
            xbuf, hin_cur,
            cw1 + (size_t)l * EMB * HID, cb1 + (size_t)l * HID,
            cw2 + (size_t)l * HID * EMB, cb2 + (size_t)l * EMB,
            bng + (size_t)l * EMB, bnb + (size_t)l * EMB,
            outp, vn, batch, vt, N, last ? 0 : 1, (l == 0) ? 1 : 0, inv);

        float* tmp = hin_cur; hin_cur = hin_nxt; hin_nxt = tmp;
    }
}

// round 16
// speedup vs baseline: 1.4245x; 1.0584x over previous
#include <cuda_runtime.h>
#include <cuda_bf16.h>
#include <math.h>

// ---------------- problem constants ----------------
#define EMB 128
#define HID 256
#define EDIM 16
#define NGRAPH 512
#define NLAYER 3
#define MAXN 100352
#define MAXE 600064

// ---------------- scratch (device globals) ----------------
__device__ float g_hinA[(size_t)MAXN * EMB];
__device__ float g_hinB[(size_t)MAXN * EMB];
__device__ __nv_bfloat16 g_x[(size_t)MAXN * EMB];
__device__ __nv_bfloat16 g_emb[(size_t)NLAYER * MAXE * EMB];
__device__ float g_vn [NGRAPH * EMB];
__device__ float g_vt [NGRAPH * EMB];
// CSR scratch
__device__ int g_deg [MAXN];
__device__ int g_off [MAXN + 1];
__device__ int g_cur [MAXN];
__device__ int g_part[256];
__device__ int g_eids[MAXE];
__device__ int g_ssrc[MAXE];

// ---------------- helpers ----------------
__device__ __forceinline__ void red_add_v4(float* p, float4 v) {
    asm volatile("red.global.add.v4.f32 [%0], {%1,%2,%3,%4};"
                 :: "l"(p), "f"(v.x), "f"(v.y), "f"(v.z), "f"(v.w) : "memory");
}
__device__ __forceinline__ void mma_tf32(float* c, const unsigned* a, unsigned b0, unsigned b1) {
    asm volatile("mma.sync.aligned.m16n8k8.row.col.f32.tf32.tf32.f32 "
                 "{%0,%1,%2,%3},{%4,%5,%6,%7},{%8,%9},{%0,%1,%2,%3};"
                 : "+f"(c[0]), "+f"(c[1]), "+f"(c[2]), "+f"(c[3])
                 : "r"(a[0]), "r"(a[1]), "r"(a[2]), "r"(a[3]), "r"(b0), "r"(b1));
}
__device__ __forceinline__ void cp_async16(float* smem, const float* gmem) {
    unsigned s = (unsigned)__cvta_generic_to_shared(smem);
    asm volatile("cp.async.cg.shared.global [%0], [%1], 16;" :: "r"(s), "l"(gmem));
}
#define CP_COMMIT() asm volatile("cp.async.commit_group;")
#define CP_WAIT1()  asm volatile("cp.async.wait_group 1;")
#define CP_WAIT0()  asm volatile("cp.async.wait_group 0;")

// ================= CSR build (once per launch) =================
__global__ void k_count(const int* __restrict__ eidx, int* __restrict__ deg, int E) {
    int e = blockIdx.x * blockDim.x + threadIdx.x;
    if (e < E) atomicAdd(&deg[eidx[E + e]], 1);
}

__global__ void k_scan1(const int* __restrict__ deg, int* __restrict__ off,
                        int* __restrict__ part, int N) {
    __shared__ int wsum[16];
    int i = blockIdx.x * 512 + threadIdx.x;
    int lane = threadIdx.x & 31, w = threadIdx.x >> 5;
    int v = (i < N) ? deg[i] : 0;
    int x = v;
#pragma unroll
    for (int d = 1; d < 32; d <<= 1) { int y = __shfl_up_sync(0xffffffffu, x, d); if (lane >= d) x += y; }
    if (lane == 31) wsum[w] = x;
    __syncthreads();
    if (w == 0) {
        int s = (lane < 16) ? wsum[lane] : 0;
#pragma unroll
        for (int d = 1; d < 16; d <<= 1) { int y = __shfl_up_sync(0xffffffffu, s, d); if (lane >= d) s += y; }
        if (lane < 16) wsum[lane] = s;
    }
    __syncthreads();
    int base = (w > 0) ? wsum[w - 1] : 0;
    if (i < N) off[i] = base + x - v;
    if (threadIdx.x == 0) part[blockIdx.x] = wsum[15];
}

__global__ void k_scan2(int* __restrict__ part) {
    __shared__ int wsum[8];
    int tid = threadIdx.x;
    int lane = tid & 31, w = tid >> 5;
    int v = part[tid];
    int x = v;
#pragma unroll
    for (int d = 1; d < 32; d <<= 1) { int y = __shfl_up_sync(0xffffffffu, x, d); if (lane >= d) x += y; }
    if (lane == 31) wsum[w] = x;
    __syncthreads();
    if (w == 0) {
        int s = (lane < 8) ? wsum[lane] : 0;
#pragma unroll
        for (int d = 1; d < 8; d <<= 1) { int y = __shfl_up_sync(0xffffffffu, s, d); if (lane >= d) s += y; }
        if (lane < 8) wsum[lane] = s;
    }
    __syncthreads();
    int base = (w > 0) ? wsum[w - 1] : 0;
    part[tid] = base + x - v;
}

__global__ void k_scan3(int* __restrict__ off, int* __restrict__ cur,
                        const int* __restrict__ part, int N, int E) {
    int i = blockIdx.x * 512 + threadIdx.x;
    if (i < N) {
        int o = off[i] + part[blockIdx.x];
        off[i] = o;
        cur[i] = o;
    }
    if (i == 0) off[N] = E;
}

__global__ void k_scatter(const int* __restrict__ eidx, int* __restrict__ cur,
                          int* __restrict__ eids, int* __restrict__ ssrc, int E) {
    int e = blockIdx.x * blockDim.x + threadIdx.x;
    if (e < E) {
        int pos = atomicAdd(&cur[eidx[E + e]], 1);
        eids[pos] = e;
        ssrc[pos] = eidx[e];
    }
}

// ---------------- kernel 0: init vn ----------------
__global__ void k_init_vn(const float* __restrict__ vn_emb, float* __restrict__ vn) {
    int i = blockIdx.x * blockDim.x + threadIdx.x;
    if (i < NGRAPH * EMB) vn[i] = vn_emb[i & (EMB - 1)];
}

// ---------------- kernel 1: hin = h + vn[batch]; vt += segsum(hin) (layer 0) ----------------
__global__ void k_hin_vt(const float* __restrict__ h, const int* __restrict__ batch,
                         const float* __restrict__ vn, float* __restrict__ hin,
                         float* __restrict__ vt, int N) {
    int lane = threadIdx.x;
    int row  = threadIdx.y;
    int base = blockIdx.x * 64;
    float4 acc = make_float4(0.f, 0.f, 0.f, 0.f);
    int gcur = -1;
    for (int it = 0; it < 8; it++) {
        int i = base + it * 8 + row;
        if (i >= N) break;
        int g = batch[i];
        const float4 hv = *(const float4*)&h[(size_t)i * EMB + lane * 4];
        const float4 vv = *(const float4*)&vn[(size_t)g * EMB + lane * 4];
        float4 s = make_float4(hv.x + vv.x, hv.y + vv.y, hv.z + vv.z, hv.w + vv.w);
        *(float4*)&hin[(size_t)i * EMB + lane * 4] = s;
        if (g != gcur) {
            if (gcur >= 0) red_add_v4(&vt[(size_t)gcur * EMB + lane * 4], acc);
            acc = make_float4(0.f, 0.f, 0.f, 0.f);
            gcur = g;
        }
        acc.x += s.x; acc.y += s.y; acc.z += s.z; acc.w += s.w;
    }
    if (gcur >= 0) red_add_v4(&vt[(size_t)gcur * EMB + lane * 4], acc);
}

// ---------------- kernel 1b: vt += segsum(hin) ----------------
__global__ void k_vt(const float* __restrict__ hin, const int* __restrict__ batch,
                     float* __restrict__ vt, int N) {
    int lane = threadIdx.x;
    int row  = threadIdx.y;
    int base = blockIdx.x * 64;
    float4 acc = make_float4(0.f, 0.f, 0.f, 0.f);
    int gcur = -1;
    for (int it = 0; it < 8; it++) {
        int i = base + it * 8 + row;
        if (i >= N) break;
        int g = batch[i];
        const float4 s = *(const float4*)&hin[(size_t)i * EMB + lane * 4];
        if (g != gcur) {
            if (gcur >= 0) red_add_v4(&vt[(size_t)gcur * EMB + lane * 4], acc);
            acc = make_float4(0.f, 0.f, 0.f, 0.f);
            gcur = g;
        }
        acc.x += s.x; acc.y += s.y; acc.z += s.z; acc.w += s.w;
    }
    if (gcur >= 0) red_add_v4(&vt[(size_t)gcur * EMB + lane * 4], acc);
}

// ---------------- kernel 2a: 3-layer edge embedding GEMM (gather once) ----------------
// For all 3 layers: emb_l[pos] = bf16(ea[eids[pos]] @ We_l + be_l). As staged ONCE.
#define AS_STR 20
#define WE_STR 136

__global__ __launch_bounds__(256) void k_edge_emb3(
    const float* __restrict__ ea, const int* __restrict__ eids,
    const float* __restrict__ We /*[3,16,128]*/, const float* __restrict__ be /*[3,128]*/,
    __nv_bfloat16* __restrict__ emb /*[3, MAXE, EMB]*/, int E) {
    __shared__ float As[64 * AS_STR];
    __shared__ float sW[NLAYER * EDIM * WE_STR];   // ~26 KB

    int tid = threadIdx.x;
    int wid = tid >> 5, lane = tid & 31;
    int g = lane >> 2, t = lane & 3;
    int warp_m = wid >> 2;
    int warp_n = wid & 3;
    long long base = (long long)blockIdx.x * 64;

    // stage all 3 weight matrices
#pragma unroll
    for (int l = 0; l < NLAYER; l++) {
#pragma unroll
        for (int p = 0; p < 8; p++) {
            int li = tid + p * 256;
            int k = li >> 7, c = li & 127;
            sW[l * EDIM * WE_STR + k * WE_STR + c] = We[(size_t)l * EDIM * EMB + k * EMB + c];
        }
    }
    // stage gathered ea rows ONCE
    {
        int row = tid >> 2, cg = tid & 3;
        long long pos = base + row;
        float4 v = make_float4(0.f, 0.f, 0.f, 0.f);
        if (pos < E) {
            int eid = eids[pos];
            v = *(const float4*)&ea[(size_t)eid * EDIM + cg * 4];
        }
        float* d = &As[row * AS_STR + cg * 4];
        d[0] = v.x; d[1] = v.y; d[2] = v.z; d[3] = v.w;
    }
    __syncthreads();

    // load A fragments once (shared across the 3 layer GEMMs)
    unsigned a[2][2][4];   // [ks][mt][frag]
#pragma unroll
    for (int ks = 0; ks < 2; ks++) {
        int kl = ks * 8;
#pragma unroll
        for (int mt = 0; mt < 2; mt++) {
            int r = warp_m * 32 + mt * 16 + g;
            a[ks][mt][0] = __float_as_uint(As[r * AS_STR + kl + t]);
            a[ks][mt][1] = __float_as_uint(As[(r + 8) * AS_STR + kl + t]);
            a[ks][mt][2] = __float_as_uint(As[r * AS_STR + kl + t + 4]);
            a[ks][mt][3] = __float_as_uint(As[(r + 8) * AS_STR + kl + t + 4]);
        }
    }

#pragma unroll
    for (int l = 0; l < NLAYER; l++) {
        const float* sWl = &sW[l * EDIM * WE_STR];
        float c[2][4][4];
#pragma unroll
        for (int mt = 0; mt < 2; mt++)
#pragma unroll
            for (int nt = 0; nt < 4; nt++)
#pragma unroll
                for (int j = 0; j < 4; j++) c[mt][nt][j] = 0.f;

#pragma unroll
        for (int ks = 0; ks < 2; ks++) {
            int kl = ks * 8;
#pragma unroll
            for (int nt = 0; nt < 4; nt++) {
                int col = warp_n * 32 + nt * 8 + g;
                unsigned b0 = __float_as_uint(sWl[(kl + t) * WE_STR + col]);
                unsigned b1r = __float_as_uint(sWl[(kl + t + 4) * WE_STR + col]);
                mma_tf32(c[0][nt], a[ks][0], b0, b1r);
                mma_tf32(c[1][nt], a[ks][1], b0, b1r);
            }
        }

        __nv_bfloat16* embl = emb + (size_t)l * MAXE * EMB;
#pragma unroll
        for (int nt = 0; nt < 4; nt++) {
            int col = warp_n * 32 + nt * 8 + t * 2;
            float bv0 = __ldg(&be[l * EMB + col]), bv1 = __ldg(&be[l * EMB + col + 1]);
#pragma unroll
            for (int mt = 0; mt < 2; mt++) {
#pragma unroll
                for (int half = 0; half < 2; half++) {
                    int row = warp_m * 32 + mt * 16 + g + half * 8;
                    long long pos = base + row;
                    if (pos < E) {
                        __nv_bfloat162 o = __floats2bfloat162_rn(
                            c[mt][nt][half * 2] + bv0, c[mt][nt][half * 2 + 1] + bv1);
                        *(__nv_bfloat162*)&embl[(size_t)pos * EMB + col] = o;
                    }
                }
            }
        }
    }
}

// ---------------- kernel 2b: slim CSR aggregation (R11 form) ----------------
__global__ __launch_bounds__(256) void k_agg_csr(
    const float* __restrict__ hin, const __nv_bfloat16* __restrict__ emb,
    const int* __restrict__ ssrc, const int* __restrict__ off,
    __nv_bfloat16* __restrict__ xout, int N) {
    int tid = threadIdx.x;
    int lane = tid & 31;
    int node = blockIdx.x * 8 + (tid >> 5);
    if (node >= N) return;
    int beg = off[node], end = off[node + 1];

    float4 hn = *(const float4*)&hin[(size_t)node * EMB + lane * 4];
    float4 acc = make_float4(0.f, 0.f, 0.f, 0.f);
    int p = beg;

    for (; p + 2 <= end; p += 2) {
        int s0 = ssrc[p], s1 = ssrc[p + 1];
        uint2 u0 = *(const uint2*)&emb[(size_t)p * EMB + lane * 4];
        uint2 u1 = *(const uint2*)&emb[(size_t)(p + 1) * EMB + lane * 4];
        float4 x0 = *(const float4*)&hin[(size_t)s0 * EMB + lane * 4];
        float4 x1 = *(const float4*)&hin[(size_t)s1 * EMB + lane * 4];
        acc.x += fmaxf(x0.x + __uint_as_float(u0.x << 16), 0.f)
               + fmaxf(x1.x + __uint_as_float(u1.x << 16), 0.f);
        acc.y += fmaxf(x0.y + __uint_as_float(u0.x & 0xFFFF0000u), 0.f)
               + fmaxf(x1.y + __uint_as_float(u1.x & 0xFFFF0000u), 0.f);
        acc.z += fmaxf(x0.z + __uint_as_float(u0.y << 16), 0.f)
               + fmaxf(x1.z + __uint_as_float(u1.y << 16), 0.f);
        acc.w += fmaxf(x0.w + __uint_as_float(u0.y & 0xFFFF0000u), 0.f)
               + fmaxf(x1.w + __uint_as_float(u1.y & 0xFFFF0000u), 0.f);
    }
    if (p < end) {
        int s0 = ssrc[p];
        uint2 u0 = *(const uint2*)&emb[(size_t)p * EMB + lane * 4];
        float4 x0 = *(const float4*)&hin[(size_t)s0 * EMB + lane * 4];
        acc.x += fmaxf(x0.x + __uint_as_float(u0.x << 16), 0.f);
        acc.y += fmaxf(x0.y + __uint_as_float(u0.x & 0xFFFF0000u), 0.f);
        acc.z += fmaxf(x0.z + __uint_as_float(u0.y << 16), 0.f);
        acc.w += fmaxf(x0.w + __uint_as_float(u0.y & 0xFFFF0000u), 0.f);
    }
    acc.x += hn.x; acc.y += hn.y; acc.z += hn.z; acc.w += hn.w;
    __nv_bfloat162 p0 = __floats2bfloat162_rn(acc.x, acc.y);
    __nv_bfloat162 p1 = __floats2bfloat162_rn(acc.z, acc.w);
    uint2 o;
    o.x = *(unsigned*)&p0;
    o.y = *(unsigned*)&p1;
    *(uint2*)&xout[(size_t)node * EMB + lane * 4] = o;
}

// ---------------- kernel 3: tensor-core node MLP (tf32, cp.async, occ=2, R11 form) ----------------
#define XS_STR 132
#define HS_STR 260
#define W1_STR 264
#define W2_STR 136
#define UB_FLOATS (64 * HS_STR)
#define WD_FLOATS (2 * 32 * W2_STR)
#define MLP_SMEM_FLOATS (UB_FLOATS + WD_FLOATS)

__global__ __launch_bounds__(256, 2) void k_node_mlp(
    const __nv_bfloat16* __restrict__ xin, const float* __restrict__ hin,
    const float* __restrict__ W1, const float* __restrict__ b1,
    const float* __restrict__ W2, const float* __restrict__ b2,
    const float* __restrict__ gamma, const float* __restrict__ beta,
    float* __restrict__ out, const float* __restrict__ vnn,
    const int* __restrict__ batch, int N, int mode, float inv) {
    extern __shared__ float smf[];
    float* Xs = smf;
    float* Hs = smf;
    float* Wd = smf + UB_FLOATS;

    int tid = threadIdx.x;
    int wid = tid >> 5, lane = tid & 31;
    int g = lane >> 2, t = lane & 3;
    int warp_m = wid >> 2;
    int warp_n = wid & 3;
    int base = blockIdx.x * 64;

#pragma unroll
    for (int p = 0; p < 8; p++) {
        int li = tid + p * 256;
        int row = li >> 5;
        int c4 = (li & 31) * 4;
        int node = base + row;
        float4 v = make_float4(0.f, 0.f, 0.f, 0.f);
        if (node < N) {
            uint2 u = *(const uint2*)&xin[(size_t)node * EMB + c4];
            v.x = __uint_as_float(u.x << 16);
            v.y = __uint_as_float(u.x & 0xFFFF0000u);
            v.z = __uint_as_float(u.y << 16);
            v.w = __uint_as_float(u.y & 0xFFFF0000u);
        }
        *(float4*)&Xs[row * XS_STR + c4] = v;
    }

    float c1[2][8][4];
#pragma unroll
    for (int mt = 0; mt < 2; mt++)
#pragma unroll
        for (int nt = 0; nt < 8; nt++)
#pragma unroll
            for (int j = 0; j < 4; j++) c1[mt][nt][j] = 0.f;

    {
#pragma unroll
        for (int p = 0; p < 4; p++) {
            int idx4 = tid + p * 256;
            int row = idx4 >> 6, c4 = idx4 & 63;
            cp_async16(&Wd[row * W1_STR + c4 * 4], &W1[(size_t)row * 256 + c4 * 4]);
        }
        CP_COMMIT();
    }

    for (int kc = 0; kc < 8; kc++) {
        if (kc < 7) {
            float* db = Wd + ((kc + 1) & 1) * (16 * W1_STR);
#pragma unroll
            for (int p = 0; p < 4; p++) {
                int idx4 = tid + p * 256;
                int row = idx4 >> 6, c4 = idx4 & 63;
                cp_async16(&db[row * W1_STR + c4 * 4],
                           &W1[(size_t)((kc + 1) * 16 + row) * 256 + c4 * 4]);
            }
            CP_COMMIT();
            CP_WAIT1();
        } else {
            CP_WAIT0();
        }
        __syncthreads();
        const float* Wb = Wd + (kc & 1) * (16 * W1_STR);
#pragma unroll
        for (int ks = 0; ks < 2; ks++) {
            int kl = ks * 8;
            int kg = kc * 16 + kl;
            unsigned a[2][4];
#pragma unroll
            for (int mt = 0; mt < 2; mt++) {
                int r = warp_m * 32 + mt * 16 + g;
                const float* x0 = &Xs[r * XS_STR + kg + t];
                const float* x8 = &Xs[(r + 8) * XS_STR + kg + t];
                a[mt][0] = __float_as_uint(x0[0]);
                a[mt][1] = __float_as_uint(x8[0]);
                a[mt][2] = __float_as_uint(x0[4]);
                a[mt][3] = __float_as_uint(x8[4]);
            }
#pragma unroll
            for (int nt = 0; nt < 8; nt++) {
                int col = warp_n * 64 + nt * 8 + g;
                unsigned b0 = __float_as_uint(Wb[(kl + t) * W1_STR + col]);
                unsigned b1r = __float_as_uint(Wb[(kl + t + 4) * W1_STR + col]);
                mma_tf32(c1[0][nt], a[0], b0, b1r);
                mma_tf32(c1[1][nt], a[1], b0, b1r);
            }
        }
        __syncthreads();
    }

#pragma unroll
    for (int nt = 0; nt < 8; nt++) {
        int c0 = warp_n * 64 + nt * 8 + t * 2;
        float bb0 = __ldg(&b1[c0]);
        float bb1 = __ldg(&b1[c0 + 1]);
#pragma unroll
        for (int mt = 0; mt < 2; mt++) {
            int r = warp_m * 32 + mt * 16 + g;
            Hs[r * HS_STR + c0]           = fmaxf(c1[mt][nt][0] + bb0, 0.f);
            Hs[r * HS_STR + c0 + 1]       = fmaxf(c1[mt][nt][1] + bb1, 0.f);
            Hs[(r + 8) * HS_STR + c0]     = fmaxf(c1[mt][nt][2] + bb0, 0.f);
            Hs[(r + 8) * HS_STR + c0 + 1] = fmaxf(c1[mt][nt][3] + bb1, 0.f);
        }
    }

    float c2[2][4][4];
#pragma unroll
    for (int mt = 0; mt < 2; mt++)
#pragma unroll
        for (int nt = 0; nt < 4; nt++)
#pragma unroll
            for (int j = 0; j < 4; j++) c2[mt][nt][j] = 0.f;

    {
#pragma unroll
        for (int p = 0; p < 4; p++) {
            int idx4 = tid + p * 256;
            int row = idx4 >> 5, c4 = idx4 & 31;
            cp_async16(&Wd[row * W2_STR + c4 * 4], &W2[(size_t)row * 128 + c4 * 4]);
        }
        CP_COMMIT();
    }

    for (int kc = 0; kc < 8; kc++) {
        if (kc < 7) {
            float* db = Wd + ((kc + 1) & 1) * (32 * W2_STR);
#pragma unroll
            for (int p = 0; p < 4; p++) {
                int idx4 = tid + p * 256;
                int row = idx4 >> 5, c4 = idx4 & 31;
                cp_async16(&db[row * W2_STR + c4 * 4],
                           &W2[(size_t)((kc + 1) * 32 + row) * 128 + c4 * 4]);
            }
            CP_COMMIT();
            CP_WAIT1();
        } else {
            CP_WAIT0();
        }
        __syncthreads();
        const float* Wb = Wd + (kc & 1) * (32 * W2_STR);
#pragma unroll
        for (int ks = 0; ks < 4; ks++) {
            int kl = ks * 8;
            int kg = kc * 32 + kl;
            unsigned a[2][4];
#pragma unroll
            for (int mt = 0; mt < 2; mt++) {
                int r = warp_m * 32 + mt * 16 + g;
                const float* x0 = &Hs[r * HS_STR + kg + t];
                const float* x8 = &Hs[(r + 8) * HS_STR + kg + t];
                a[mt][0] = __float_as_uint(x0[0]);
                a[mt][1] = __float_as_uint(x8[0]);
                a[mt][2] = __float_as_uint(x0[4]);
                a[mt][3] = __float_as_uint(x8[4]);
            }
#pragma unroll
            for (int nt = 0; nt < 4; nt++) {
                int col = warp_n * 32 + nt * 8 + g;
                unsigned b0 = __float_as_uint(Wb[(kl + t) * W2_STR + col]);
                unsigned b1r = __float_as_uint(Wb[(kl + t + 4) * W2_STR + col]);
                mma_tf32(c2[0][nt], a[0], b0, b1r);
                mma_tf32(c2[1][nt], a[1], b0, b1r);
            }
        }
        __syncthreads();
    }

    int bg[2][2];
    if (mode) {
#pragma unroll
        for (int mt = 0; mt < 2; mt++)
#pragma unroll
            for (int half = 0; half < 2; half++) {
                int node = base + warp_m * 32 + mt * 16 + g + half * 8;
                bg[mt][half] = (node < N) ? batch[node] : 0;
            }
    }
#pragma unroll
    for (int nt = 0; nt < 4; nt++) {
        int col = warp_n * 32 + nt * 8 + t * 2;
        float bv0 = __ldg(&b2[col]),          bv1 = __ldg(&b2[col + 1]);
        float gv0 = __ldg(&gamma[col]) * inv, gv1 = __ldg(&gamma[col + 1]) * inv;
        float ev0 = __ldg(&beta[col]),        ev1 = __ldg(&beta[col + 1]);
#pragma unroll
        for (int mt = 0; mt < 2; mt++) {
#pragma unroll
            for (int half = 0; half < 2; half++) {
                int row = warp_m * 32 + mt * 16 + g + half * 8;
                int node = base + row;
                if (node < N) {
                    float z0 = c2[mt][nt][half * 2]     + bv0;
                    float z1 = c2[mt][nt][half * 2 + 1] + bv1;
                    z0 = z0 * gv0 + ev0;
                    z1 = z1 * gv1 + ev1;
                    if (mode) { z0 = fmaxf(z0, 0.f); z1 = fmaxf(z1, 0.f); }
                    float2 hr = *(const float2*)&hin[(size_t)node * EMB + col];
                    z0 += hr.x; z1 += hr.y;
                    if (mode) {
                        float2 vv = *(const float2*)&vnn[(size_t)bg[mt][half] * EMB + col];
                        z0 += vv.x; z1 += vv.y;
                    }
                    *(float2*)&out[(size_t)node * EMB + col] = make_float2(z0, z1);
                }
            }
        }
    }
}

// ---------------- kernel 4: virtual-node MLP ----------------
__global__ __launch_bounds__(256) void k_vn_mlp(
    const float* __restrict__ vt, float* __restrict__ vn,
    const float* __restrict__ w1, const float* __restrict__ b1,
    const float* __restrict__ g1, const float* __restrict__ be1,
    const float* __restrict__ w2, const float* __restrict__ b2,
    const float* __restrict__ g2, const float* __restrict__ be2, float inv) {
    __shared__ float sv[EMB];
    __shared__ float sm1[HID];
    int g = blockIdx.x;
    int tid = threadIdx.x;
    if (tid < EMB) sv[tid] = vt[(size_t)g * EMB + tid] + vn[(size_t)g * EMB + tid];
    __syncthreads();
    {
        int j = tid;
        float s = b1[j];
#pragma unroll 8
        for (int k = 0; k < EMB; k++) s += sv[k] * w1[(size_t)k * HID + j];
        s = s * (g1[j] * inv) + be1[j];
        sm1[j] = fmaxf(s, 0.f);
    }
    __syncthreads();
    if (tid < EMB) {
        int c = tid;
        float s = b2[c];
#pragma unroll 8
        for (int j = 0; j < HID; j++) s += sm1[j] * w2[(size_t)j * EMB + c];
        s = s * (g2[c] * inv) + be2[c];
        vn[(size_t)g * EMB + c] += fmaxf(s, 0.f);
    }
}

// ---------------- host orchestration ----------------
extern "C" void kernel_launch(void* const* d_in, const int* in_sizes, int n_in,
                              void* d_out, int out_size) {
    if (n_in < 21) return;

    const float* input_feature = (const float*)d_in[0];
    const int* edge_index;
    const float* edge_attr;
    long long E;
    if ((long long)in_sizes[1] < (long long)in_sizes[2]) {
        edge_index = (const int*)d_in[1];
        edge_attr  = (const float*)d_in[2];
        E = in_sizes[1] / 2;
    } else {
        edge_index = (const int*)d_in[2];
        edge_attr  = (const float*)d_in[1];
        E = in_sizes[2] / 2;
    }
    const int* batch = (const int*)d_in[3];
    int N = in_sizes[0] / EMB;

    const float* vn_emb = (const float*)d_in[4];
    const float* cew = (const float*)d_in[5];
    const float* ceb = (const float*)d_in[6];
    const float* cw1 = (const float*)d_in[7];
    const float* cb1 = (const float*)d_in[8];
    const float* cw2 = (const float*)d_in[9];
    const float* cb2 = (const float*)d_in[10];
    const float* bng = (const float*)d_in[11];
    const float* bnb = (const float*)d_in[12];
    const float* vw1 = (const float*)d_in[13];
    const float* vb1 = (const float*)d_in[14];
    const float* vg1 = (const float*)d_in[15];
    const float* vbe1 = (const float*)d_in[16];
    const float* vw2 = (const float*)d_in[17];
    const float* vb2 = (const float*)d_in[18];
    const float* vg2 = (const float*)d_in[19];
    const float* vbe2 = (const float*)d_in[20];

    float *hinA, *hinB, *vn, *vt;
    __nv_bfloat16 *xbuf, *embbuf;
    int *deg, *off, *cur, *part, *eids, *ssrc;
    cudaGetSymbolAddress((void**)&hinA, g_hinA);
    cudaGetSymbolAddress((void**)&hinB, g_hinB);
    cudaGetSymbolAddress((void**)&xbuf, g_x);
    cudaGetSymbolAddress((void**)&embbuf, g_emb);
    cudaGetSymbolAddress((void**)&vn, g_vn);
    cudaGetSymbolAddress((void**)&vt, g_vt);
    cudaGetSymbolAddress((void**)&deg, g_deg);
    cudaGetSymbolAddress((void**)&off, g_off);
    cudaGetSymbolAddress((void**)&cur, g_cur);
    cudaGetSymbolAddress((void**)&part, g_part);
    cudaGetSymbolAddress((void**)&eids, g_eids);
    cudaGetSymbolAddress((void**)&ssrc, g_ssrc);

    cudaFuncSetAttribute(k_node_mlp, cudaFuncAttributeMaxDynamicSharedMemorySize,
                         MLP_SMEM_FLOATS * (int)sizeof(float));

    const float inv = 1.0f / sqrtf(1.0f + 1e-5f);

    // ---- CSR build ----
    int NB = (N + 511) / 512;
    cudaMemsetAsync(deg, 0, (size_t)N * sizeof(int));
    cudaMemsetAsync(part, 0, 256 * sizeof(int));
    k_count<<<(int)((E + 255) / 256), 256>>>(edge_index, deg, (int)E);
    k_scan1<<<NB, 512>>>(deg, off, part, N);
    k_scan2<<<1, 256>>>(part);
    k_scan3<<<NB, 512>>>(off, cur, part, N, (int)E);
    k_scatter<<<(int)((E + 255) / 256), 256>>>(edge_index, cur, eids, ssrc, (int)E);

    k_init_vn<<<(NGRAPH * EMB + 255) / 256, 256>>>(vn_emb, vn);

    int nblk = (N + 63) / 64;
    int ablk = (N + 7) / 8;
    int emblk = (int)((E + 63) / 64);
    size_t mlp_smem = MLP_SMEM_FLOATS * sizeof(float);

    // all 3 layers' edge embeddings in one pass (ea gathered once)
    k_edge_emb3<<<emblk, 256>>>(edge_attr, eids, cew, ceb, embbuf, (int)E);

    cudaMemsetAsync(vt, 0, (size_t)NGRAPH * EMB * sizeof(float));
    k_hin_vt<<<nblk, dim3(32, 8)>>>(input_feature, batch, vn, hinA, vt, N);

    float* hin_cur = hinA;
    float* hin_nxt = hinB;
    for (int l = 0; l < NLAYER; l++) {
        int last = (l == NLAYER - 1);

        k_agg_csr<<<ablk, 256>>>(hin_cur, embbuf + (size_t)l * MAXE * EMB,
                                 ssrc, off, xbuf, N);

        if (!last) {
            k_vn_mlp<<<NGRAPH, 256>>>(vt, vn,
                                      vw1 + (size_t)l * EMB * HID, vb1 + (size_t)l * HID,
                                      vg1 + (size_t)l * HID, vbe1 + (size_t)l * HID,
                                      vw2 + (size_t)l * HID * EMB, vb2 + (size_t)l * EMB,
                                      vg2 + (size_t)l * EMB, vbe2 + (size_t)l * EMB, inv);
        }

        float* outp = last ? (float*)d_out : hin_nxt;
        k_node_mlp<<<nblk, 256, mlp_smem>>>(
            xbuf, hin_cur,
            cw1 + (size_t)l * EMB * HID, cb1 + (size_t)l * HID,
            cw2 + (size_t)l * HID * EMB, cb2 + (size_t)l * EMB,
            bng + (size_t)l * EMB, bnb + (size_t)l * EMB,
            outp, vn, batch, N, last ? 0 : 1, inv);

        if (l == 0) {
            cudaMemsetAsync(vt, 0, (size_t)NGRAPH * EMB * sizeof(float));
            k_vt<<<nblk, dim3(32, 8)>>>(hin_nxt, batch, vt, N);
        }

        float* tmp = hin_cur; hin_cur = hin_nxt; hin_nxt = tmp;
    }
}